// round 15
// baseline (speedup 1.0000x reference)
#include <cuda_runtime.h>
#include <math.h>
#include <stdint.h>

#define S   1024
#define H   2048
#define NH  16
#define HD  128
#define E   16
#define TOPK 4
#define IM  1408
#define IS  5632
#define EPS 1e-6f

// ---------------- scratch (device globals) ----------------
__device__ float g_h1[S*H];
__device__ float g_q[S*H];
__device__ float g_k[S*H];
__device__ float g_v[S*H];
__device__ float g_attn[S*H];
__device__ float g_h2[S*H];
__device__ float g_gs[S*IS];
__device__ float g_us[S*IS];
__device__ float g_logits[S*E];
__device__ float g_sg[S];
__device__ int   g_cnt[E];
__device__ int   g_tk_e[S*TOPK];
__device__ int   g_tk_slot[S*TOPK];
__device__ float g_tk_w[S*TOPK];
__device__ int   g_tok[E*S];
__device__ float g_gbuf[E*S*IM];
__device__ float g_ubuf[E*S*IM];
__device__ float g_ybuf[E*S*H];
__device__ float g_part[18874368];
__device__ __align__(16) float g_zero[4];   // zero-initialized, never written

// ---------------- block reductions ----------------
__device__ __forceinline__ float blockReduceSum(float v) {
    __shared__ float sh[33];
    int lane = threadIdx.x & 31, wid = threadIdx.x >> 5;
    #pragma unroll
    for (int o = 16; o; o >>= 1) v += __shfl_down_sync(0xffffffffu, v, o);
    if (lane == 0) sh[wid] = v;
    __syncthreads();
    int nw = (blockDim.x + 31) >> 5;
    float t = (threadIdx.x < nw) ? sh[threadIdx.x] : 0.f;
    if (wid == 0) {
        #pragma unroll
        for (int o = 16; o; o >>= 1) t += __shfl_down_sync(0xffffffffu, t, o);
        if (lane == 0) sh[32] = t;
    }
    __syncthreads();
    float r = sh[32];
    __syncthreads();
    return r;
}

// ---------------- tf32 helpers ----------------
__device__ __forceinline__ uint32_t f2tf32(float f) {
    uint32_t r;
    asm("cvt.rna.tf32.f32 %0, %1;" : "=r"(r) : "f"(f));
    return r;
}
__device__ __forceinline__ float roundtf(float f) {
    return __uint_as_float(f2tf32(f));
}

__device__ __forceinline__ void mma_tf32(float& d0, float& d1, float& d2, float& d3,
                                         uint32_t a0, uint32_t a1, uint32_t a2, uint32_t a3,
                                         uint32_t b0, uint32_t b1) {
    asm volatile(
        "mma.sync.aligned.m16n8k8.row.col.f32.tf32.tf32.f32 "
        "{%0,%1,%2,%3}, {%4,%5,%6,%7}, {%8,%9}, {%0,%1,%2,%3};"
        : "+f"(d0), "+f"(d1), "+f"(d2), "+f"(d3)
        : "r"(a0), "r"(a1), "r"(a2), "r"(a3), "r"(b0), "r"(b1));
}

__device__ __forceinline__ void cp_async16(uint32_t smem_addr, const void* gptr) {
    asm volatile("cp.async.cg.shared.global [%0], [%1], 16;"
                 :: "r"(smem_addr), "l"(gptr));
}
__device__ __forceinline__ void cp_commit() {
    asm volatile("cp.async.commit_group;" ::: "memory");
}
__device__ __forceinline__ void cp_wait0() {
    asm volatile("cp.async.wait_group 0;" ::: "memory");
}

// ---------------- TF32 GEMM: A via cp.async (pre-rounded), B via LDG+cvt+STS ----------------
#define LDA_SH 20
#define LDB_SH 136
#define STG_SZ (128 * LDA_SH)

struct GSet { const float* B; float* C; const float* bias; const float* B2; float* C2; };
struct GSets { GSet s[3]; };

// split-K partial layout (primary batches): part + ((set*inner+ib)*nsplit+sp)*(Mfull*N)
__global__ void __launch_bounds__(128, 2)
tgemm_kernel(const float* __restrict__ A, GSets sets,
             int M, int N, int K, int lda, int ldb, int ldc,
             long long sA, long long sB, long long sC,
             float alpha, const int* __restrict__ mcnt,
             int inner, int nsplit, int ksz,
             float* __restrict__ part,
             const int* __restrict__ rowidx_all,
             int inner1, int Malt,
             const float* __restrict__ A2, int lda2, long long aSlice,
             int ldb2, long long bSlice, int ldc2, long long cSlice,
             const float* __restrict__ zeroPtr)
{
    const int z = blockIdx.z;
    const int sp  = z % nsplit;
    const int t   = z / nsplit;
    const int ib  = t % inner;
    const int set = t / inner;
    const bool alt = (ib >= inner1);

    const int Mfull = M;
    if (alt) M = Malt;
    else if (mcnt) M = mcnt[ib];
    const int m0 = blockIdx.y * 128;
    if (m0 >= M) return;
    const int n0 = blockIdx.x * 128;

    const float* Ab;  int ldaE, ldbE;
    const float* Bb;
    const float* bias;
    const int* rowidx;
    float* Cb;
    int ldcc;
    if (!alt) {
        Ab = A + (long long)ib * sA;            ldaE = lda;
        Bb = sets.s[set].B + (long long)ib * sB; ldbE = ldb;
        bias = sets.s[set].bias;
        rowidx = rowidx_all ? rowidx_all + (long long)ib * S : nullptr;
        if (nsplit > 1) {
            Cb = part + (((long long)set * inner + ib) * nsplit + sp) * ((long long)Mfull * N);
            ldcc = N;
            bias = nullptr;
        } else {
            Cb = sets.s[set].C + (long long)ib * sC;
            ldcc = ldc;
        }
    } else {
        int sl = ib - inner1;
        Ab = A2 + (long long)sl * aSlice;             ldaE = lda2;
        Bb = sets.s[set].B2 + (long long)sl * bSlice; ldbE = ldb2;
        Cb = sets.s[set].C2 + (long long)sl * cSlice;
        ldcc = ldc2;
        bias = nullptr;
        rowidx = nullptr;
    }

    int kbeg = (!alt && nsplit > 1) ? sp * ksz : 0;
    int kend = (!alt && nsplit > 1) ? kbeg + ksz : K;
    if (kend > K) kend = K;

    __shared__ uint32_t As[2][STG_SZ];
    __shared__ uint32_t Bs[2][STG_SZ];

    const int tid  = threadIdx.x;
    const int lane = tid & 31;
    const int warp = tid >> 5;
    const int wm   = (warp & 1) * 64;
    const int wn   = (warp >> 1) * 64;
    const int g    = lane >> 2;
    const int tg   = lane & 3;

    const int arow = tid >> 2;
    const int acq  = (tid & 3) * 4;
    const int brow = tid >> 5;
    const int bn4  = (tid & 31) * 4;

    // loop-invariant addressing (incl. rowidx, resolved once)
    const float* aRowP[4];
    #pragma unroll
    for (int p = 0; p < 4; p++) {
        int r = m0 + arow + p * 32;
        if (r < M) {
            long long gr = rowidx ? (long long)rowidx[r] : (long long)r;
            aRowP[p] = Ab + gr * ldaE;
        } else aRowP[p] = nullptr;
    }
    const float* bCol = (n0 + bn4 < N) ? Bb + n0 + bn4 : nullptr;

    // cp.async destinations for A (fixed per thread per stage)
    uint32_t aDst[2];
    {
        uint32_t asb = (uint32_t)__cvta_generic_to_shared(&As[0][0]);
        aDst[0] = asb + (arow * LDA_SH + acq) * 4;
        aDst[1] = aDst[0] + STG_SZ * 4;
    }

    auto issue_A = [&](int st, int kt) {
        #pragma unroll
        for (int p = 0; p < 4; p++) {
            const float* src = aRowP[p] ? aRowP[p] + kt + acq : zeroPtr;
            cp_async16(aDst[st] + p * 32 * LDA_SH * 4, src);
        }
        cp_commit();
    };

    float4 bvr[4];
    const float4 zf4 = make_float4(0.f, 0.f, 0.f, 0.f);
    auto load_B = [&](int kt) {
        #pragma unroll
        for (int p = 0; p < 4; p++)
            bvr[p] = bCol ? *reinterpret_cast<const float4*>(bCol + (long long)(kt + brow + 4 * p) * ldbE) : zf4;
    };
    auto store_B = [&](uint32_t* Bs_) {
        #pragma unroll
        for (int p = 0; p < 4; p++) {
            int k = brow + p * 4;
            uint4 v = make_uint4(f2tf32(bvr[p].x), f2tf32(bvr[p].y),
                                 f2tf32(bvr[p].z), f2tf32(bvr[p].w));
            *reinterpret_cast<uint4*>(&Bs_[k * LDB_SH + bn4]) = v;
        }
    };

    float acc[4][8][4];
    #pragma unroll
    for (int i = 0; i < 4; i++)
        #pragma unroll
        for (int j = 0; j < 8; j++)
            #pragma unroll
            for (int c = 0; c < 4; c++) acc[i][j][c] = 0.f;

    // prologue
    issue_A(0, kbeg);
    load_B(kbeg);
    store_B(Bs[0]);
    cp_wait0();
    __syncthreads();

    int p = 0;
    for (int kt = kbeg; kt < kend; kt += 16) {
        const bool has_next = (kt + 16 < kend);
        if (has_next) {
            issue_A(p ^ 1, kt + 16);
            load_B(kt + 16);
        }

        const uint32_t* Asp = As[p];
        const uint32_t* Bsp = Bs[p];
        #pragma unroll
        for (int kk = 0; kk < 16; kk += 8) {
            uint32_t af[4][4];
            #pragma unroll
            for (int mt = 0; mt < 4; mt++) {
                const uint32_t* base = &Asp[(wm + mt * 16 + g) * LDA_SH + kk + tg];
                af[mt][0] = base[0];
                af[mt][1] = base[8 * LDA_SH];
                af[mt][2] = base[4];
                af[mt][3] = base[8 * LDA_SH + 4];
            }
            uint32_t bf[8][2];
            #pragma unroll
            for (int nt = 0; nt < 8; nt++) {
                int n = wn + nt * 8 + g;
                bf[nt][0] = Bsp[(kk + tg) * LDB_SH + n];
                bf[nt][1] = Bsp[(kk + tg + 4) * LDB_SH + n];
            }
            #pragma unroll
            for (int mt = 0; mt < 4; mt++)
                #pragma unroll
                for (int nt = 0; nt < 8; nt++)
                    mma_tf32(acc[mt][nt][0], acc[mt][nt][1], acc[mt][nt][2], acc[mt][nt][3],
                             af[mt][0], af[mt][1], af[mt][2], af[mt][3],
                             bf[nt][0], bf[nt][1]);
        }

        if (has_next) {
            store_B(Bs[p ^ 1]);
            cp_wait0();
            __syncthreads();
            p ^= 1;
        }
    }

    #pragma unroll
    for (int mt = 0; mt < 4; mt++) {
        int r0 = m0 + wm + mt * 16 + g;
        int r1 = r0 + 8;
        #pragma unroll
        for (int nt = 0; nt < 8; nt++) {
            int col = n0 + wn + nt * 8 + 2 * tg;
            if (col >= N) continue;
            float b0 = bias ? bias[col]     : 0.f;
            float b1 = bias ? bias[col + 1] : 0.f;
            if (r0 < M) {
                float2 v = make_float2(acc[mt][nt][0] * alpha + b0,
                                       acc[mt][nt][1] * alpha + b1);
                *reinterpret_cast<float2*>(&Cb[(long long)r0 * ldcc + col]) = v;
            }
            if (r1 < M) {
                float2 v = make_float2(acc[mt][nt][2] * alpha + b0,
                                       acc[mt][nt][3] * alpha + b1);
                *reinterpret_cast<float2*>(&Cb[(long long)r1 * ldcc + col]) = v;
            }
        }
    }
}

// logits split-K reduce + zero cnt
__global__ void reduce_logits_zero_kernel(const float4* __restrict__ P,
                                          float4* __restrict__ C, int* __restrict__ cnt,
                                          int nsplit, long long sSplit4, long long total4)
{
    long long i = (long long)blockIdx.x * blockDim.x + threadIdx.x;
    if (blockIdx.x == 0 && threadIdx.x < E) cnt[threadIdx.x] = 0;
    if (i >= total4) return;
    float4 s = P[i];
    for (int sp = 1; sp < nsplit; sp++) {
        float4 t = P[sp * sSplit4 + i];
        s.x += t.x; s.y += t.y; s.z += t.z; s.w += t.w;
    }
    C[i] = s;
}

// QKV split-K reduce with fused bias + RoPE (3 splits). Grid: S x 256.
__global__ void reduce_qkv_rope_kernel(const float* __restrict__ P,
                                       float* __restrict__ q, float* __restrict__ k,
                                       float* __restrict__ v,
                                       const float* __restrict__ qb,
                                       const float* __restrict__ kb,
                                       const float* __restrict__ vb,
                                       const int* __restrict__ pos)
{
    const long long SH = (long long)S * H;
    const int t = blockIdx.x;
    const int tid = threadIdx.x;
    const int h  = tid >> 4;
    const int d4 = (tid & 15) * 4;
    const long long rowb = (long long)t * H;
    const int cb = h * HD + d4;
    float p = (float)pos[t];

    float cs[4], sn[4];
    #pragma unroll
    for (int j = 0; j < 4; j++) {
        float inv = exp2f(-(float)(d4 + j) * 0.31143075889569023f);
        sincosf(p * inv, &sn[j], &cs[j]);
    }

    #pragma unroll
    for (int set = 0; set < 2; set++) {
        const float* P0 = P + ((long long)set * 3 + 0) * SH + rowb;
        const float* P1 = P + ((long long)set * 3 + 1) * SH + rowb;
        const float* P2 = P + ((long long)set * 3 + 2) * SH + rowb;
        const float* bias = set ? kb : qb;
        float* dst = set ? k : q;
        float4 a0 = *reinterpret_cast<const float4*>(P0 + cb);
        float4 a1 = *reinterpret_cast<const float4*>(P1 + cb);
        float4 a2 = *reinterpret_cast<const float4*>(P2 + cb);
        float4 b0 = *reinterpret_cast<const float4*>(P0 + cb + 64);
        float4 b1 = *reinterpret_cast<const float4*>(P1 + cb + 64);
        float4 b2 = *reinterpret_cast<const float4*>(P2 + cb + 64);
        float4 bi0 = *reinterpret_cast<const float4*>(bias + cb);
        float4 bi1 = *reinterpret_cast<const float4*>(bias + cb + 64);
        float x1[4] = {a0.x + a1.x + a2.x + bi0.x, a0.y + a1.y + a2.y + bi0.y,
                       a0.z + a1.z + a2.z + bi0.z, a0.w + a1.w + a2.w + bi0.w};
        float x2[4] = {b0.x + b1.x + b2.x + bi1.x, b0.y + b1.y + b2.y + bi1.y,
                       b0.z + b1.z + b2.z + bi1.z, b0.w + b1.w + b2.w + bi1.w};
        float4 o1, o2;
        o1.x = x1[0] * cs[0] - x2[0] * sn[0];  o2.x = x2[0] * cs[0] + x1[0] * sn[0];
        o1.y = x1[1] * cs[1] - x2[1] * sn[1];  o2.y = x2[1] * cs[1] + x1[1] * sn[1];
        o1.z = x1[2] * cs[2] - x2[2] * sn[2];  o2.z = x2[2] * cs[2] + x1[2] * sn[2];
        o1.w = x1[3] * cs[3] - x2[3] * sn[3];  o2.w = x2[3] * cs[3] + x1[3] * sn[3];
        *reinterpret_cast<float4*>(dst + rowb + cb)      = o1;
        *reinterpret_cast<float4*>(dst + rowb + cb + 64) = o2;
    }

    {
        const float* P0 = P + 6 * SH + rowb;
        const float* P1 = P + 7 * SH + rowb;
        const float* P2 = P + 8 * SH + rowb;
        #pragma unroll
        for (int r = 0; r < 2; r++) {
            int col = (tid + r * 256) * 4;
            float4 a = *reinterpret_cast<const float4*>(P0 + col);
            float4 b = *reinterpret_cast<const float4*>(P1 + col);
            float4 c = *reinterpret_cast<const float4*>(P2 + col);
            float4 bi = *reinterpret_cast<const float4*>(vb + col);
            *reinterpret_cast<float4*>(v + rowb + col) =
                make_float4(a.x + b.x + c.x + bi.x, a.y + b.y + c.y + bi.y,
                            a.z + b.z + c.z + bi.z, a.w + b.w + c.w + bi.w);
        }
    }
}

// fused: x2 = sum4(Oproj partials) + hidden; h2 = round_tf32(rmsnorm(x2)*ln2w); sg = sigmoid(h2 . wsg)
__global__ void oproj_rms_sgate_kernel(const float* __restrict__ P,
                                       const float* __restrict__ hidden,
                                       const float* __restrict__ w,
                                       const float* __restrict__ wsg,
                                       float* __restrict__ h2, float* __restrict__ sg)
{
    __shared__ float row[H];
    const long long SH = (long long)S * H;
    int t = blockIdx.x;
    const long long rowb = (long long)t * H;
    float s = 0.f;
    for (int i = threadIdx.x; i < H / 4; i += blockDim.x) {
        int c = i * 4;
        float4 a = *reinterpret_cast<const float4*>(P + rowb + c);
        float4 b = *reinterpret_cast<const float4*>(P + SH + rowb + c);
        float4 d = *reinterpret_cast<const float4*>(P + 2 * SH + rowb + c);
        float4 e = *reinterpret_cast<const float4*>(P + 3 * SH + rowb + c);
        float4 hd = *reinterpret_cast<const float4*>(hidden + rowb + c);
        float4 x = make_float4(a.x + b.x + d.x + e.x + hd.x,
                               a.y + b.y + d.y + e.y + hd.y,
                               a.z + b.z + d.z + e.z + hd.z,
                               a.w + b.w + d.w + e.w + hd.w);
        *reinterpret_cast<float4*>(&row[c]) = x;
        s += x.x * x.x + x.y * x.y + x.z * x.z + x.w * x.w;
    }
    s = blockReduceSum(s);
    float scale = rsqrtf(s / (float)H + EPS);
    float d = 0.f;
    for (int i = threadIdx.x; i < H / 4; i += blockDim.x) {
        int c = i * 4;
        float4 x = *reinterpret_cast<const float4*>(&row[c]);
        float4 ww = *reinterpret_cast<const float4*>(w + c);
        float4 gg = *reinterpret_cast<const float4*>(wsg + c);
        float4 o = make_float4(roundtf(x.x * scale * ww.x), roundtf(x.y * scale * ww.y),
                               roundtf(x.z * scale * ww.z), roundtf(x.w * scale * ww.w));
        *reinterpret_cast<float4*>(h2 + rowb + c) = o;
        d += o.x * gg.x + o.y * gg.y + o.z * gg.z + o.w * gg.w;
    }
    d = blockReduceSum(d);
    if (threadIdx.x == 0) sg[t] = 1.f / (1.f + __expf(-d));
}

// ---------------- flash attention v2 (epilogue rounds output) ----------------
#define FAQ_LD 132
#define FAK_LD 132
#define FAV_LD 136
#define FAP_LD 36
#define FA_QS   0
#define FA_KV0  (64*FAQ_LD)
#define FA_KVST (32*FAK_LD + 32*FAV_LD)
#define FA_PS   (FA_KV0 + 2*FA_KVST)
#define FA_TOT  (FA_PS + 4*16*FAP_LD)
#define ATTN_SCALE 0.08838834764831845f

__global__ void __launch_bounds__(128)
flash_attn_kernel(const float* __restrict__ Q, const float* __restrict__ K,
                  const float* __restrict__ V, float* __restrict__ O)
{
    extern __shared__ uint32_t sh[];
    const int qb   = (gridDim.x - 1) - blockIdx.x;
    const int hh   = blockIdx.y;
    const int tid  = threadIdx.x;
    const int lane = tid & 31;
    const int warp = tid >> 5;
    const int g    = lane >> 2;
    const int tg   = lane & 3;
    const int wm   = warp * 16;
    const int q0   = qb * 64;
    const long long hoff = (long long)hh * HD;

    const uint32_t shbase = (uint32_t)__cvta_generic_to_shared(sh);

    #pragma unroll
    for (int j = 0; j < 16; j++) {
        int idx = tid + 128 * j;
        int r = idx >> 5, c4 = (idx & 31) * 4;
        float4 t = *reinterpret_cast<const float4*>(&Q[(long long)(q0 + r) * H + hoff + c4]);
        uint4 v = make_uint4(f2tf32(t.x * ATTN_SCALE), f2tf32(t.y * ATTN_SCALE),
                             f2tf32(t.z * ATTN_SCALE), f2tf32(t.w * ATTN_SCALE));
        *reinterpret_cast<uint4*>(&sh[FA_QS + r * FAQ_LD + c4]) = v;
    }

    const int ldrow = tid >> 5;
    const int ldc4  = (tid & 31) * 4;

    auto issue_chunk = [&](int c, int s) {
        uint32_t kbase = shbase + (FA_KV0 + s * FA_KVST) * 4;
        uint32_t vbase = kbase + 32 * FAK_LD * 4;
        #pragma unroll
        for (int j = 0; j < 8; j++) {
            int r = ldrow + 4 * j;
            long long gofs = (long long)(c * 32 + r) * H + hoff + ldc4;
            cp_async16(kbase + (r * FAK_LD + ldc4) * 4, &K[gofs]);
            cp_async16(vbase + (r * FAV_LD + ldc4) * 4, &V[gofs]);
        }
        cp_commit();
    };

    float Oacc[16][4];
    #pragma unroll
    for (int nt = 0; nt < 16; nt++)
        #pragma unroll
        for (int c = 0; c < 4; c++) Oacc[nt][c] = 0.f;
    float m0r = -1e30f, m1r = -1e30f, l0r = 0.f, l1r = 0.f;

    uint32_t* Pw = &sh[FA_PS + warp * 16 * FAP_LD];
    const int nc = 2 * qb + 2;

    issue_chunk(0, 0);

    for (int c = 0; c < nc; c++) {
        cp_wait0();
        __syncthreads();
        if (c + 1 < nc) issue_chunk(c + 1, (c + 1) & 1);

        const uint32_t* K_ = &sh[FA_KV0 + (c & 1) * FA_KVST];
        const uint32_t* V_ = K_ + 32 * FAK_LD;

        float Sacc[4][4];
        #pragma unroll
        for (int nt = 0; nt < 4; nt++)
            #pragma unroll
            for (int cc = 0; cc < 4; cc++) Sacc[nt][cc] = 0.f;

        #pragma unroll
        for (int kk = 0; kk < 128; kk += 8) {
            uint32_t a0 = sh[FA_QS + (wm + g) * FAQ_LD + kk + tg];
            uint32_t a1 = sh[FA_QS + (wm + g + 8) * FAQ_LD + kk + tg];
            uint32_t a2 = sh[FA_QS + (wm + g) * FAQ_LD + kk + tg + 4];
            uint32_t a3 = sh[FA_QS + (wm + g + 8) * FAQ_LD + kk + tg + 4];
            #pragma unroll
            for (int nt = 0; nt < 4; nt++) {
                uint32_t b0 = K_[(nt * 8 + g) * FAK_LD + kk + tg];
                uint32_t b1 = K_[(nt * 8 + g) * FAK_LD + kk + tg + 4];
                mma_tf32(Sacc[nt][0], Sacc[nt][1], Sacc[nt][2], Sacc[nt][3],
                         a0, a1, a2, a3, b0, b1);
            }
        }

        if (c >= 2 * qb) {
            int r0g = q0 + wm + g, r1g = r0g + 8;
            #pragma unroll
            for (int nt = 0; nt < 4; nt++) {
                int c0 = c * 32 + nt * 8 + 2 * tg, c1 = c0 + 1;
                if (c0 > r0g) Sacc[nt][0] = -1e30f;
                if (c1 > r0g) Sacc[nt][1] = -1e30f;
                if (c0 > r1g) Sacc[nt][2] = -1e30f;
                if (c1 > r1g) Sacc[nt][3] = -1e30f;
            }
        }

        float rmax0 = -1e30f, rmax1 = -1e30f;
        #pragma unroll
        for (int nt = 0; nt < 4; nt++) {
            rmax0 = fmaxf(rmax0, fmaxf(Sacc[nt][0], Sacc[nt][1]));
            rmax1 = fmaxf(rmax1, fmaxf(Sacc[nt][2], Sacc[nt][3]));
        }
        rmax0 = fmaxf(rmax0, __shfl_xor_sync(0xffffffffu, rmax0, 1));
        rmax0 = fmaxf(rmax0, __shfl_xor_sync(0xffffffffu, rmax0, 2));
        rmax1 = fmaxf(rmax1, __shfl_xor_sync(0xffffffffu, rmax1, 1));
        rmax1 = fmaxf(rmax1, __shfl_xor_sync(0xffffffffu, rmax1, 2));

        float nm0 = fmaxf(m0r, rmax0), nm1 = fmaxf(m1r, rmax1);
        float al0 = __expf(m0r - nm0), al1 = __expf(m1r - nm1);
        float sum0 = 0.f, sum1 = 0.f;
        #pragma unroll
        for (int nt = 0; nt < 4; nt++) {
            float p00 = __expf(Sacc[nt][0] - nm0);
            float p01 = __expf(Sacc[nt][1] - nm0);
            float p10 = __expf(Sacc[nt][2] - nm1);
            float p11 = __expf(Sacc[nt][3] - nm1);
            sum0 += p00 + p01; sum1 += p10 + p11;
            int cl = nt * 8 + 2 * tg;
            Pw[g * FAP_LD + cl]           = f2tf32(p00);
            Pw[g * FAP_LD + cl + 1]       = f2tf32(p01);
            Pw[(g + 8) * FAP_LD + cl]     = f2tf32(p10);
            Pw[(g + 8) * FAP_LD + cl + 1] = f2tf32(p11);
        }
        sum0 += __shfl_xor_sync(0xffffffffu, sum0, 1);
        sum0 += __shfl_xor_sync(0xffffffffu, sum0, 2);
        sum1 += __shfl_xor_sync(0xffffffffu, sum1, 1);
        sum1 += __shfl_xor_sync(0xffffffffu, sum1, 2);
        l0r = l0r * al0 + sum0;
        l1r = l1r * al1 + sum1;
        m0r = nm0; m1r = nm1;

        #pragma unroll
        for (int nt = 0; nt < 16; nt++) {
            Oacc[nt][0] *= al0; Oacc[nt][1] *= al0;
            Oacc[nt][2] *= al1; Oacc[nt][3] *= al1;
        }

        __syncwarp();

        #pragma unroll
        for (int kk = 0; kk < 32; kk += 8) {
            uint32_t a0 = Pw[g * FAP_LD + kk + tg];
            uint32_t a1 = Pw[(g + 8) * FAP_LD + kk + tg];
            uint32_t a2 = Pw[g * FAP_LD + kk + tg + 4];
            uint32_t a3 = Pw[(g + 8) * FAP_LD + kk + tg + 4];
            #pragma unroll
            for (int nt = 0; nt < 16; nt++) {
                uint32_t b0 = V_[(kk + tg) * FAV_LD + nt * 8 + g];
                uint32_t b1 = V_[(kk + tg + 4) * FAV_LD + nt * 8 + g];
                mma_tf32(Oacc[nt][0], Oacc[nt][1], Oacc[nt][2], Oacc[nt][3],
                         a0, a1, a2, a3, b0, b1);
            }
        }
    }

    float inv0 = 1.f / l0r, inv1 = 1.f / l1r;
    long long r0 = q0 + wm + g, r1 = r0 + 8;
    #pragma unroll
    for (int nt = 0; nt < 16; nt++) {
        int c = nt * 8 + 2 * tg;
        *reinterpret_cast<float2*>(&O[r0 * H + hoff + c]) =
            make_float2(roundtf(Oacc[nt][0] * inv0), roundtf(Oacc[nt][1] * inv0));
        *reinterpret_cast<float2*>(&O[r1 * H + hoff + c]) =
            make_float2(roundtf(Oacc[nt][2] * inv1), roundtf(Oacc[nt][3] * inv1));
    }
}

// ---------------- elementwise / norm ----------------
// rmsnorm with tf32-rounded output (h1 feeds GEMM A-side via cp.async)
__global__ void rmsnorm_kernel(const float* __restrict__ x, const float* __restrict__ w,
                               float* __restrict__ y) {
    int t = blockIdx.x;
    const float4* xr = reinterpret_cast<const float4*>(x + (long long)t * H);
    const float4* w4 = reinterpret_cast<const float4*>(w);
    float4* yr = reinterpret_cast<float4*>(y + (long long)t * H);
    float s = 0.f;
    for (int i = threadIdx.x; i < H / 4; i += blockDim.x) {
        float4 v = xr[i];
        s += v.x * v.x + v.y * v.y + v.z * v.z + v.w * v.w;
    }
    s = blockReduceSum(s);
    float scale = rsqrtf(s / (float)H + EPS);
    for (int i = threadIdx.x; i < H / 4; i += blockDim.x) {
        float4 v = xr[i], ww = w4[i];
        yr[i] = make_float4(roundtf(v.x * scale * ww.x), roundtf(v.y * scale * ww.y),
                            roundtf(v.z * scale * ww.z), roundtf(v.w * scale * ww.w));
    }
}

// merged silu*mul with tf32-rounded output: grid (S, 20)
__global__ void silumul_all_kernel(float4* __restrict__ gbuf, const float4* __restrict__ ubuf,
                                   float* __restrict__ gs, const float* __restrict__ us,
                                   const int* __restrict__ cnt)
{
    int e = blockIdx.y, slot = blockIdx.x;
    float4* gp; const float4* up;
    if (e < E) {
        if (slot >= cnt[e]) return;
        long long base = ((long long)e * S + slot) * (IM / 4);
        gp = gbuf + base;
        up = ubuf + base;
    } else {
        long long off = (long long)slot * IS + (e - E) * 1408;
        gp = reinterpret_cast<float4*>(gs + off);
        up = reinterpret_cast<const float4*>(us + off);
    }
    for (int i = threadIdx.x; i < IM / 4; i += blockDim.x) {
        float4 x = gp[i], y = up[i];
        x.x = roundtf((x.x / (1.f + __expf(-x.x))) * y.x);
        x.y = roundtf((x.y / (1.f + __expf(-x.y))) * y.y);
        x.z = roundtf((x.z / (1.f + __expf(-x.z))) * y.z);
        x.w = roundtf((x.w / (1.f + __expf(-x.w))) * y.w);
        gp[i] = x;
    }
}

// ---------------- MoE routing ----------------
__global__ void routing_kernel(const float* __restrict__ logits, int* __restrict__ cnt,
                               int* __restrict__ tke, int* __restrict__ tks,
                               float* __restrict__ tkw, int* __restrict__ tok) {
    int t = blockIdx.x * blockDim.x + threadIdx.x;
    if (t >= S) return;
    float p[E];
    float mx = -3.4e38f;
    #pragma unroll
    for (int e = 0; e < E; e++) { p[e] = logits[t * E + e]; mx = fmaxf(mx, p[e]); }
    float sum = 0.f;
    #pragma unroll
    for (int e = 0; e < E; e++) { p[e] = __expf(p[e] - mx); sum += p[e]; }
    float inv = 1.f / sum;
    #pragma unroll
    for (int e = 0; e < E; e++) p[e] *= inv;
    int ids[TOPK]; float ws[TOPK]; float wsum = 0.f;
    #pragma unroll
    for (int k = 0; k < TOPK; k++) {
        float bv = -1.f; int bi = 0;
        #pragma unroll
        for (int e = 0; e < E; e++) if (p[e] > bv) { bv = p[e]; bi = e; }
        ids[k] = bi; ws[k] = bv; wsum += bv; p[bi] = -2.f;
    }
    float wi = 1.f / wsum;
    #pragma unroll
    for (int k = 0; k < TOPK; k++) {
        int slot = atomicAdd(&cnt[ids[k]], 1);
        tke[t * TOPK + k] = ids[k];
        tks[t * TOPK + k] = slot;
        tkw[t * TOPK + k] = ws[k] * wi;
        tok[ids[k] * S + slot] = t;
    }
}

// fused combine: shared = sum of 4 down-partial slabs (in part); out = sg*shared + Σ w*y
__global__ void combine_kernel(const float* __restrict__ P, const float* __restrict__ sg,
                               const float* __restrict__ ybuf,
                               const int* __restrict__ tke, const int* __restrict__ tks,
                               const float* __restrict__ tkw, float* __restrict__ out) {
    const long long SH = (long long)S * H;
    int t = blockIdx.x;
    float gg = sg[t];
    int e0 = tke[t*4+0], e1 = tke[t*4+1], e2 = tke[t*4+2], e3 = tke[t*4+3];
    int s0 = tks[t*4+0], s1 = tks[t*4+1], s2 = tks[t*4+2], s3 = tks[t*4+3];
    float w0 = tkw[t*4+0], w1 = tkw[t*4+1], w2 = tkw[t*4+2], w3 = tkw[t*4+3];
    const float4* y0 = reinterpret_cast<const float4*>(ybuf + ((long long)e0 * S + s0) * H);
    const float4* y1 = reinterpret_cast<const float4*>(ybuf + ((long long)e1 * S + s1) * H);
    const float4* y2 = reinterpret_cast<const float4*>(ybuf + ((long long)e2 * S + s2) * H);
    const float4* y3 = reinterpret_cast<const float4*>(ybuf + ((long long)e3 * S + s3) * H);
    const long long rowb = (long long)t * H;
    float4* o = reinterpret_cast<float4*>(out + rowb);
    for (int i = threadIdx.x; i < H / 4; i += blockDim.x) {
        int c = i * 4;
        float4 p0 = *reinterpret_cast<const float4*>(P + rowb + c);
        float4 p1 = *reinterpret_cast<const float4*>(P + SH + rowb + c);
        float4 p2 = *reinterpret_cast<const float4*>(P + 2 * SH + rowb + c);
        float4 p3 = *reinterpret_cast<const float4*>(P + 3 * SH + rowb + c);
        float4 a = make_float4(p0.x + p1.x + p2.x + p3.x, p0.y + p1.y + p2.y + p3.y,
                               p0.z + p1.z + p2.z + p3.z, p0.w + p1.w + p2.w + p3.w);
        float4 b0 = y0[i], b1 = y1[i], b2 = y2[i], b3 = y3[i];
        o[i] = make_float4(
            gg * a.x + w0 * b0.x + w1 * b1.x + w2 * b2.x + w3 * b3.x,
            gg * a.y + w0 * b0.y + w1 * b1.y + w2 * b2.y + w3 * b3.y,
            gg * a.z + w0 * b0.z + w1 * b1.z + w2 * b2.z + w3 * b3.z,
            gg * a.w + w0 * b0.w + w1 * b1.w + w2 * b2.w + w3 * b3.w);
    }
}

// ---------------- host orchestration ----------------
static inline void gemm_ext(const float* A, const GSets& sets, int nsets,
                            int M, int N, int K, int lda, int ldb, int ldc,
                            long long sA, long long sB, long long sC,
                            float alpha, const int* mcnt, int inner,
                            int nsplit, int ksz, float* part, const int* rowidx,
                            int inner1, int Malt,
                            const float* A2, int lda2, long long aSlice,
                            int ldb2, long long bSlice, int ldc2, long long cSlice,
                            int maxMtiles, const float* zeroPtr) {
    dim3 grid((N + 127) / 128, maxMtiles, nsets * inner * nsplit);
    tgemm_kernel<<<grid, 128>>>(A, sets, M, N, K, lda, ldb, ldc, sA, sB, sC,
                                alpha, mcnt, inner, nsplit, ksz, part, rowidx,
                                inner1, Malt, A2, lda2, aSlice, ldb2, bSlice, ldc2, cSlice,
                                zeroPtr);
}

static inline void gemm_multi(const float* A, const GSets& sets, int nsets,
                              int M, int N, int K, int lda, int ldb, int ldc,
                              long long sA, long long sB, long long sC,
                              float alpha, const int* mcnt, int inner,
                              int nsplit, int ksz, float* part,
                              const int* rowidx, const float* zeroPtr) {
    gemm_ext(A, sets, nsets, M, N, K, lda, ldb, ldc, sA, sB, sC, alpha,
             mcnt, inner, nsplit, ksz, part, rowidx,
             inner, 0, nullptr, 0, 0, 0, 0, 0, 0, (M + 127) / 128, zeroPtr);
}

extern "C" void kernel_launch(void* const* d_in, const int* in_sizes, int n_in,
                              void* d_out, int out_size) {
    const int*   positions = (const int*)  d_in[0];
    const float* hidden    = (const float*)d_in[1];
    const float* ln1       = (const float*)d_in[2];
    const float* ln2       = (const float*)d_in[3];
    const float* q_w       = (const float*)d_in[4];
    const float* q_b       = (const float*)d_in[5];
    const float* k_w       = (const float*)d_in[6];
    const float* k_b       = (const float*)d_in[7];
    const float* v_w       = (const float*)d_in[8];
    const float* v_b       = (const float*)d_in[9];
    const float* o_w       = (const float*)d_in[10];
    const float* router_w  = (const float*)d_in[11];
    const float* we_gate   = (const float*)d_in[12];
    const float* we_up     = (const float*)d_in[13];
    const float* we_down   = (const float*)d_in[14];
    const float* ws_gate   = (const float*)d_in[15];
    const float* ws_up     = (const float*)d_in[16];
    const float* ws_down   = (const float*)d_in[17];
    const float* wsg       = (const float*)d_in[18];
    float* out = (float*)d_out;

    float *h1, *q, *k, *v, *attn, *h2, *gs, *us;
    float *logits, *sgv, *gbuf, *ubuf, *ybuf, *tkw, *part, *zero;
    int *cnt, *tke, *tks, *tok;
    cudaGetSymbolAddress((void**)&h1,     g_h1);
    cudaGetSymbolAddress((void**)&q,      g_q);
    cudaGetSymbolAddress((void**)&k,      g_k);
    cudaGetSymbolAddress((void**)&v,      g_v);
    cudaGetSymbolAddress((void**)&attn,   g_attn);
    cudaGetSymbolAddress((void**)&h2,     g_h2);
    cudaGetSymbolAddress((void**)&gs,     g_gs);
    cudaGetSymbolAddress((void**)&us,     g_us);
    cudaGetSymbolAddress((void**)&logits, g_logits);
    cudaGetSymbolAddress((void**)&sgv,    g_sg);
    cudaGetSymbolAddress((void**)&cnt,    g_cnt);
    cudaGetSymbolAddress((void**)&tke,    g_tk_e);
    cudaGetSymbolAddress((void**)&tks,    g_tk_slot);
    cudaGetSymbolAddress((void**)&tkw,    g_tk_w);
    cudaGetSymbolAddress((void**)&tok,    g_tok);
    cudaGetSymbolAddress((void**)&gbuf,   g_gbuf);
    cudaGetSymbolAddress((void**)&ubuf,   g_ubuf);
    cudaGetSymbolAddress((void**)&ybuf,   g_ybuf);
    cudaGetSymbolAddress((void**)&part,   g_part);
    cudaGetSymbolAddress((void**)&zero,   g_zero);

    cudaFuncSetAttribute(flash_attn_kernel,
                         cudaFuncAttributeMaxDynamicSharedMemorySize, FA_TOT * 4);

    // --- pre-attention norm (tf32-rounded out) + fused QKV (split-K 3) + bias/RoPE reduce ---
    rmsnorm_kernel<<<S, 256>>>(hidden, ln1, h1);
    {
        GSets s{};
        s.s[0] = {q_w, nullptr, nullptr, nullptr, nullptr};
        s.s[1] = {k_w, nullptr, nullptr, nullptr, nullptr};
        s.s[2] = {v_w, nullptr, nullptr, nullptr, nullptr};
        gemm_multi(h1, s, 3, S, H, H, H, H, H, 0, 0, 0, 1.f, nullptr, 1,
                   3, 688, part, nullptr, zero);
        reduce_qkv_rope_kernel<<<S, 256>>>(part, q, k, v, q_b, k_b, v_b, positions);
    }

    // --- fused flash attention (rounds its output) ---
    flash_attn_kernel<<<dim3(S / 64, NH), 128, FA_TOT * 4>>>(q, k, v, attn);

    // --- O proj (split-K 4) + fused residual/rmsnorm/sgate (rounds h2) ---
    {
        GSets s{};
        s.s[0] = {o_w, nullptr, nullptr, nullptr, nullptr};
        gemm_multi(attn, s, 1, S, H, H, H, H, 0, 0, 0, 0,
                   1.f, nullptr, 1, 4, 512, part, nullptr, zero);
        oproj_rms_sgate_kernel<<<S, 256>>>(part, hidden, ln2, wsg, h2, sgv);
    }

    // --- router (split-K 8) + dispatch ---
    {
        GSets s{};
        s.s[0] = {router_w, nullptr, nullptr, nullptr, nullptr};
        gemm_multi(h2, s, 1, S, E, H, H, E, E, 0, 0, 0,
                   1.f, nullptr, 1, 8, 256, part, nullptr, zero);
        reduce_logits_zero_kernel<<<(S * E / 4 + 255) / 256, 256>>>(
            (const float4*)part, (float4*)logits, cnt,
            8, (long long)S * E / 4, (long long)S * E / 4);
    }
    routing_kernel<<<(S + 255) / 256, 256>>>(logits, cnt, tke, tks, tkw, tok);

    // --- MERGED gate/up: 16 routed experts + 4 shared-expert N-slices ---
    {
        GSets s{};
        s.s[0] = {we_gate, gbuf, nullptr, ws_gate, gs};
        s.s[1] = {we_up,   ubuf, nullptr, ws_up,   us};
        gemm_ext(h2, s, 2, S, IM, H, H, IM, IM,
                 0, (long long)H * IM, (long long)S * IM,
                 1.f, cnt, 20, 1, 0, nullptr, tok,
                 16, S, h2, H, 0, IS, 1408, IS, 1408, S / 128, zero);
    }
    silumul_all_kernel<<<dim3(S, 20), 256>>>((float4*)gbuf, (const float4*)ubuf,
                                             gs, us, cnt);

    // --- MERGED down: 16 routed experts + 4 shared-expert K-slices (partials) ---
    {
        GSets s{};
        s.s[0] = {we_down, ybuf, nullptr, ws_down, part};
        gemm_ext(gbuf, s, 1, S, H, IM, IM, H, H,
                 (long long)S * IM, (long long)IM * H, (long long)S * H,
                 1.f, cnt, 20, 1, 0, nullptr, nullptr,
                 16, S, gs, IS, 1408, H, (long long)1408 * H, H, (long long)S * H,
                 S / 128, zero);
    }

    // --- final combine (sums shared-expert partials inline) ---
    combine_kernel<<<S, 256>>>(part, sgv, ybuf, tke, tks, tkw, out);
}

// round 16
// speedup vs baseline: 2.4187x; 2.4187x over previous
#include <cuda_runtime.h>
#include <math.h>
#include <stdint.h>

#define S   1024
#define H   2048
#define NH  16
#define HD  128
#define E   16
#define TOPK 4
#define IM  1408
#define IS  5632
#define EPS 1e-6f

// ---------------- scratch (device globals) ----------------
__device__ float g_h1[S*H];
__device__ float g_q[S*H];
__device__ float g_k[S*H];
__device__ float g_v[S*H];
__device__ float g_attn[S*H];
__device__ float g_h2[S*H];
__device__ float g_gs[S*IS];
__device__ float g_us[S*IS];
__device__ float g_logits[S*E];
__device__ float g_sg[S];
__device__ int   g_cnt[E];
__device__ int   g_tk_e[S*TOPK];
__device__ int   g_tk_slot[S*TOPK];
__device__ float g_tk_w[S*TOPK];
__device__ int   g_tok[E*S];
__device__ float g_gbuf[E*S*IM];
__device__ float g_ubuf[E*S*IM];
__device__ float g_ybuf[E*S*H];
__device__ float g_part[18874368];   // up to 9 S*H slabs (75 MB)

// ---------------- block reductions ----------------
__device__ __forceinline__ float blockReduceSum(float v) {
    __shared__ float sh[33];
    int lane = threadIdx.x & 31, wid = threadIdx.x >> 5;
    #pragma unroll
    for (int o = 16; o; o >>= 1) v += __shfl_down_sync(0xffffffffu, v, o);
    if (lane == 0) sh[wid] = v;
    __syncthreads();
    int nw = (blockDim.x + 31) >> 5;
    float t = (threadIdx.x < nw) ? sh[threadIdx.x] : 0.f;
    if (wid == 0) {
        #pragma unroll
        for (int o = 16; o; o >>= 1) t += __shfl_down_sync(0xffffffffu, t, o);
        if (lane == 0) sh[32] = t;
    }
    __syncthreads();
    float r = sh[32];
    __syncthreads();
    return r;
}

// ---------------- tf32 helpers ----------------
__device__ __forceinline__ uint32_t f2tf32(float f) {
    uint32_t r;
    asm("cvt.rna.tf32.f32 %0, %1;" : "=r"(r) : "f"(f));
    return r;
}

__device__ __forceinline__ void mma_tf32(float& d0, float& d1, float& d2, float& d3,
                                         uint32_t a0, uint32_t a1, uint32_t a2, uint32_t a3,
                                         uint32_t b0, uint32_t b1) {
    asm volatile(
        "mma.sync.aligned.m16n8k8.row.col.f32.tf32.tf32.f32 "
        "{%0,%1,%2,%3}, {%4,%5,%6,%7}, {%8,%9}, {%0,%1,%2,%3};"
        : "+f"(d0), "+f"(d1), "+f"(d2), "+f"(d3)
        : "r"(a0), "r"(a1), "r"(a2), "r"(a3), "r"(b0), "r"(b1));
}

__device__ __forceinline__ void cp_async16(uint32_t smem_addr, const void* gptr) {
    asm volatile("cp.async.cg.shared.global [%0], [%1], 16;"
                 :: "r"(smem_addr), "l"(gptr));
}
__device__ __forceinline__ void cp_commit() {
    asm volatile("cp.async.commit_group;" ::: "memory");
}
__device__ __forceinline__ void cp_wait0() {
    asm volatile("cp.async.wait_group 0;" ::: "memory");
}

// ---------------- TF32 GEMM (BK=16, 128 threads, 64x64 warp tiles) ----------------
#define LDA_SH 20
#define LDB_SH 136
#define STG_SZ (128 * LDA_SH)

struct GSet { const float* B; float* C; const float* bias; const float* B2; float* C2; };
struct GSets { GSet s[3]; };

__device__ __forceinline__ void stage_load(
    float4* avr, float4* bvr,
    const float* const* aRowP, const float* const* bRowP, const float* bCol,
    int kt, int ldb, int transB, int acq, int brow)
{
    const float4 zf4 = make_float4(0.f, 0.f, 0.f, 0.f);
    #pragma unroll
    for (int p = 0; p < 4; p++)
        avr[p] = aRowP[p] ? *reinterpret_cast<const float4*>(aRowP[p] + kt + acq) : zf4;
    if (!transB) {
        #pragma unroll
        for (int p = 0; p < 4; p++)
            bvr[p] = bCol ? *reinterpret_cast<const float4*>(bCol + (long long)(kt + brow + 4 * p) * ldb) : zf4;
    } else {
        #pragma unroll
        for (int p = 0; p < 4; p++)
            bvr[p] = bRowP[p] ? *reinterpret_cast<const float4*>(bRowP[p] + kt + acq) : zf4;
    }
}

__device__ __forceinline__ void stage_store(
    uint32_t* As, uint32_t* Bs, const float4* avr, const float4* bvr,
    int transB, int arow, int acq, int brow, int bn4)
{
    #pragma unroll
    for (int p = 0; p < 4; p++) {
        int r = arow + p * 32;
        uint4 v = make_uint4(f2tf32(avr[p].x), f2tf32(avr[p].y),
                             f2tf32(avr[p].z), f2tf32(avr[p].w));
        *reinterpret_cast<uint4*>(&As[r * LDA_SH + acq]) = v;
    }
    if (!transB) {
        #pragma unroll
        for (int p = 0; p < 4; p++) {
            int k = brow + p * 4;
            uint4 v = make_uint4(f2tf32(bvr[p].x), f2tf32(bvr[p].y),
                                 f2tf32(bvr[p].z), f2tf32(bvr[p].w));
            *reinterpret_cast<uint4*>(&Bs[k * LDB_SH + bn4]) = v;
        }
    } else {
        #pragma unroll
        for (int p = 0; p < 4; p++) {
            int r = arow + p * 32;
            uint4 v = make_uint4(f2tf32(bvr[p].x), f2tf32(bvr[p].y),
                                 f2tf32(bvr[p].z), f2tf32(bvr[p].w));
            *reinterpret_cast<uint4*>(&Bs[r * LDA_SH + acq]) = v;
        }
    }
}

// split-K partial layout (primary batches): part + ((set*inner+ib)*nsplit+sp)*(Mfull*N)
__global__ void __launch_bounds__(128, 2)
tgemm_kernel(const float* __restrict__ A, GSets sets,
             int M, int N, int K, int lda, int ldb, int ldc,
             long long sA, long long sB, long long sC,
             float alpha, int transB, const int* __restrict__ mcnt,
             int inner, int nsplit, int ksz,
             float* __restrict__ part,
             const int* __restrict__ rowidx_all,
             int inner1, int Malt,
             const float* __restrict__ A2, int lda2, long long aSlice,
             int ldb2, long long bSlice, int ldc2, long long cSlice)
{
    const int z = blockIdx.z;
    const int sp  = z % nsplit;
    const int t   = z / nsplit;
    const int ib  = t % inner;
    const int set = t / inner;
    const bool alt = (ib >= inner1);

    const int Mfull = M;
    if (alt) M = Malt;
    else if (mcnt) M = mcnt[ib];
    const int m0 = blockIdx.y * 128;
    if (m0 >= M) return;
    const int n0 = blockIdx.x * 128;

    const float* Ab;  int ldaE, ldbE;
    const float* Bb;
    const float* bias;
    const int* rowidx;
    float* Cb;
    int ldcc;
    if (!alt) {
        Ab = A + (long long)ib * sA;            ldaE = lda;
        Bb = sets.s[set].B + (long long)ib * sB; ldbE = ldb;
        bias = sets.s[set].bias;
        rowidx = rowidx_all ? rowidx_all + (long long)ib * S : nullptr;
        if (nsplit > 1) {
            Cb = part + (((long long)set * inner + ib) * nsplit + sp) * ((long long)Mfull * N);
            ldcc = N;
            bias = nullptr;
        } else {
            Cb = sets.s[set].C + (long long)ib * sC;
            ldcc = ldc;
        }
    } else {
        int sl = ib - inner1;
        Ab = A2 + (long long)sl * aSlice;             ldaE = lda2;
        Bb = sets.s[set].B2 + (long long)sl * bSlice; ldbE = ldb2;
        Cb = sets.s[set].C2 + (long long)sl * cSlice;
        ldcc = ldc2;
        bias = nullptr;
        rowidx = nullptr;
    }

    int kbeg = (!alt && nsplit > 1) ? sp * ksz : 0;
    int kend = (!alt && nsplit > 1) ? kbeg + ksz : K;
    if (kend > K) kend = K;

    __shared__ uint32_t As[2][STG_SZ];
    __shared__ uint32_t Bs[2][STG_SZ];

    const int tid  = threadIdx.x;
    const int lane = tid & 31;
    const int warp = tid >> 5;
    const int wm   = (warp & 1) * 64;
    const int wn   = (warp >> 1) * 64;
    const int g    = lane >> 2;
    const int tg   = lane & 3;

    const int arow = tid >> 2;
    const int acq  = (tid & 3) * 4;
    const int brow = tid >> 5;
    const int bn4  = (tid & 31) * 4;

    const float* aRowP[4];
    #pragma unroll
    for (int p = 0; p < 4; p++) {
        int r = m0 + arow + p * 32;
        if (r < M) {
            long long gr = rowidx ? (long long)rowidx[r] : (long long)r;
            aRowP[p] = Ab + gr * ldaE;
        } else aRowP[p] = nullptr;
    }
    const float* bRowP[4] = {nullptr, nullptr, nullptr, nullptr};
    const float* bCol = nullptr;
    if (!transB) {
        if (n0 + bn4 < N) bCol = Bb + n0 + bn4;
    } else {
        #pragma unroll
        for (int p = 0; p < 4; p++) {
            int r = n0 + arow + p * 32;
            if (r < N) bRowP[p] = Bb + (long long)r * ldbE;
        }
    }

    float acc[4][8][4];
    #pragma unroll
    for (int i = 0; i < 4; i++)
        #pragma unroll
        for (int j = 0; j < 8; j++)
            #pragma unroll
            for (int c = 0; c < 4; c++) acc[i][j][c] = 0.f;

    float4 avr[4], bvr[4];

    stage_load(avr, bvr, aRowP, bRowP, bCol, kbeg, ldbE, transB, acq, brow);
    stage_store(As[0], Bs[0], avr, bvr, transB, arow, acq, brow, bn4);
    __syncthreads();

    int p = 0;
    for (int kt = kbeg; kt < kend; kt += 16) {
        const bool has_next = (kt + 16 < kend);
        if (has_next)
            stage_load(avr, bvr, aRowP, bRowP, bCol, kt + 16, ldbE, transB, acq, brow);

        const uint32_t* Asp = As[p];
        const uint32_t* Bsp = Bs[p];
        #pragma unroll
        for (int kk = 0; kk < 16; kk += 8) {
            uint32_t af[4][4];
            #pragma unroll
            for (int mt = 0; mt < 4; mt++) {
                const uint32_t* base = &Asp[(wm + mt * 16 + g) * LDA_SH + kk + tg];
                af[mt][0] = base[0];
                af[mt][1] = base[8 * LDA_SH];
                af[mt][2] = base[4];
                af[mt][3] = base[8 * LDA_SH + 4];
            }
            uint32_t bf[8][2];
            if (!transB) {
                #pragma unroll
                for (int nt = 0; nt < 8; nt++) {
                    int n = wn + nt * 8 + g;
                    bf[nt][0] = Bsp[(kk + tg) * LDB_SH + n];
                    bf[nt][1] = Bsp[(kk + tg + 4) * LDB_SH + n];
                }
            } else {
                #pragma unroll
                for (int nt = 0; nt < 8; nt++) {
                    int n = wn + nt * 8 + g;
                    bf[nt][0] = Bsp[n * LDA_SH + kk + tg];
                    bf[nt][1] = Bsp[n * LDA_SH + kk + tg + 4];
                }
            }
            #pragma unroll
            for (int mt = 0; mt < 4; mt++)
                #pragma unroll
                for (int nt = 0; nt < 8; nt++)
                    mma_tf32(acc[mt][nt][0], acc[mt][nt][1], acc[mt][nt][2], acc[mt][nt][3],
                             af[mt][0], af[mt][1], af[mt][2], af[mt][3],
                             bf[nt][0], bf[nt][1]);
        }

        if (has_next) {
            stage_store(As[1 - p], Bs[1 - p], avr, bvr, transB, arow, acq, brow, bn4);
            __syncthreads();
            p ^= 1;
        }
    }

    #pragma unroll
    for (int mt = 0; mt < 4; mt++) {
        int r0 = m0 + wm + mt * 16 + g;
        int r1 = r0 + 8;
        #pragma unroll
        for (int nt = 0; nt < 8; nt++) {
            int col = n0 + wn + nt * 8 + 2 * tg;
            if (col >= N) continue;
            float b0 = bias ? bias[col]     : 0.f;
            float b1 = bias ? bias[col + 1] : 0.f;
            if (r0 < M) {
                float2 v = make_float2(acc[mt][nt][0] * alpha + b0,
                                       acc[mt][nt][1] * alpha + b1);
                *reinterpret_cast<float2*>(&Cb[(long long)r0 * ldcc + col]) = v;
            }
            if (r1 < M) {
                float2 v = make_float2(acc[mt][nt][2] * alpha + b0,
                                       acc[mt][nt][3] * alpha + b1);
                *reinterpret_cast<float2*>(&Cb[(long long)r1 * ldcc + col]) = v;
            }
        }
    }
}

// logits split-K reduce + zero cnt
__global__ void reduce_logits_zero_kernel(const float4* __restrict__ P,
                                          float4* __restrict__ C, int* __restrict__ cnt,
                                          int nsplit, long long sSplit4, long long total4)
{
    long long i = (long long)blockIdx.x * blockDim.x + threadIdx.x;
    if (blockIdx.x == 0 && threadIdx.x < E) cnt[threadIdx.x] = 0;
    if (i >= total4) return;
    float4 s = P[i];
    for (int sp = 1; sp < nsplit; sp++) {
        float4 t = P[sp * sSplit4 + i];
        s.x += t.x; s.y += t.y; s.z += t.z; s.w += t.w;
    }
    C[i] = s;
}

// QKV split-K reduce with fused bias + RoPE (3 splits). Grid: S x 256.
__global__ void reduce_qkv_rope_kernel(const float* __restrict__ P,
                                       float* __restrict__ q, float* __restrict__ k,
                                       float* __restrict__ v,
                                       const float* __restrict__ qb,
                                       const float* __restrict__ kb,
                                       const float* __restrict__ vb,
                                       const int* __restrict__ pos)
{
    const long long SH = (long long)S * H;
    const int t = blockIdx.x;
    const int tid = threadIdx.x;
    const int h  = tid >> 4;
    const int d4 = (tid & 15) * 4;
    const long long rowb = (long long)t * H;
    const int cb = h * HD + d4;
    float p = (float)pos[t];

    float cs[4], sn[4];
    #pragma unroll
    for (int j = 0; j < 4; j++) {
        float inv = exp2f(-(float)(d4 + j) * 0.31143075889569023f);
        sincosf(p * inv, &sn[j], &cs[j]);
    }

    #pragma unroll
    for (int set = 0; set < 2; set++) {
        const float* P0 = P + ((long long)set * 3 + 0) * SH + rowb;
        const float* P1 = P + ((long long)set * 3 + 1) * SH + rowb;
        const float* P2 = P + ((long long)set * 3 + 2) * SH + rowb;
        const float* bias = set ? kb : qb;
        float* dst = set ? k : q;
        float4 a0 = *reinterpret_cast<const float4*>(P0 + cb);
        float4 a1 = *reinterpret_cast<const float4*>(P1 + cb);
        float4 a2 = *reinterpret_cast<const float4*>(P2 + cb);
        float4 b0 = *reinterpret_cast<const float4*>(P0 + cb + 64);
        float4 b1 = *reinterpret_cast<const float4*>(P1 + cb + 64);
        float4 b2 = *reinterpret_cast<const float4*>(P2 + cb + 64);
        float4 bi0 = *reinterpret_cast<const float4*>(bias + cb);
        float4 bi1 = *reinterpret_cast<const float4*>(bias + cb + 64);
        float x1[4] = {a0.x + a1.x + a2.x + bi0.x, a0.y + a1.y + a2.y + bi0.y,
                       a0.z + a1.z + a2.z + bi0.z, a0.w + a1.w + a2.w + bi0.w};
        float x2[4] = {b0.x + b1.x + b2.x + bi1.x, b0.y + b1.y + b2.y + bi1.y,
                       b0.z + b1.z + b2.z + bi1.z, b0.w + b1.w + b2.w + bi1.w};
        float4 o1, o2;
        o1.x = x1[0] * cs[0] - x2[0] * sn[0];  o2.x = x2[0] * cs[0] + x1[0] * sn[0];
        o1.y = x1[1] * cs[1] - x2[1] * sn[1];  o2.y = x2[1] * cs[1] + x1[1] * sn[1];
        o1.z = x1[2] * cs[2] - x2[2] * sn[2];  o2.z = x2[2] * cs[2] + x1[2] * sn[2];
        o1.w = x1[3] * cs[3] - x2[3] * sn[3];  o2.w = x2[3] * cs[3] + x1[3] * sn[3];
        *reinterpret_cast<float4*>(dst + rowb + cb)      = o1;
        *reinterpret_cast<float4*>(dst + rowb + cb + 64) = o2;
    }

    {
        const float* P0 = P + 6 * SH + rowb;
        const float* P1 = P + 7 * SH + rowb;
        const float* P2 = P + 8 * SH + rowb;
        #pragma unroll
        for (int r = 0; r < 2; r++) {
            int col = (tid + r * 256) * 4;
            float4 a = *reinterpret_cast<const float4*>(P0 + col);
            float4 b = *reinterpret_cast<const float4*>(P1 + col);
            float4 c = *reinterpret_cast<const float4*>(P2 + col);
            float4 bi = *reinterpret_cast<const float4*>(vb + col);
            *reinterpret_cast<float4*>(v + rowb + col) =
                make_float4(a.x + b.x + c.x + bi.x, a.y + b.y + c.y + bi.y,
                            a.z + b.z + c.z + bi.z, a.w + b.w + c.w + bi.w);
        }
    }
}

// fused: x2 = sum4(Oproj partials) + hidden; h2 = rmsnorm(x2)*ln2w; sg = sigmoid(h2 . wsg)
__global__ void oproj_rms_sgate_kernel(const float* __restrict__ P,
                                       const float* __restrict__ hidden,
                                       const float* __restrict__ w,
                                       const float* __restrict__ wsg,
                                       float* __restrict__ h2, float* __restrict__ sg)
{
    __shared__ float row[H];
    const long long SH = (long long)S * H;
    int t = blockIdx.x;
    const long long rowb = (long long)t * H;
    float s = 0.f;
    for (int i = threadIdx.x; i < H / 4; i += blockDim.x) {
        int c = i * 4;
        float4 a = *reinterpret_cast<const float4*>(P + rowb + c);
        float4 b = *reinterpret_cast<const float4*>(P + SH + rowb + c);
        float4 d = *reinterpret_cast<const float4*>(P + 2 * SH + rowb + c);
        float4 e = *reinterpret_cast<const float4*>(P + 3 * SH + rowb + c);
        float4 hd = *reinterpret_cast<const float4*>(hidden + rowb + c);
        float4 x = make_float4(a.x + b.x + d.x + e.x + hd.x,
                               a.y + b.y + d.y + e.y + hd.y,
                               a.z + b.z + d.z + e.z + hd.z,
                               a.w + b.w + d.w + e.w + hd.w);
        *reinterpret_cast<float4*>(&row[c]) = x;
        s += x.x * x.x + x.y * x.y + x.z * x.z + x.w * x.w;
    }
    s = blockReduceSum(s);
    float scale = rsqrtf(s / (float)H + EPS);
    float d = 0.f;
    for (int i = threadIdx.x; i < H / 4; i += blockDim.x) {
        int c = i * 4;
        float4 x = *reinterpret_cast<const float4*>(&row[c]);
        float4 ww = *reinterpret_cast<const float4*>(w + c);
        float4 gg = *reinterpret_cast<const float4*>(wsg + c);
        float4 o = make_float4(x.x * scale * ww.x, x.y * scale * ww.y,
                               x.z * scale * ww.z, x.w * scale * ww.w);
        *reinterpret_cast<float4*>(h2 + rowb + c) = o;
        d += o.x * gg.x + o.y * gg.y + o.z * gg.z + o.w * gg.w;
    }
    d = blockReduceSum(d);
    if (threadIdx.x == 0) sg[t] = 1.f / (1.f + __expf(-d));
}

// ---------------- flash attention v2 ----------------
#define FAQ_LD 132
#define FAK_LD 132
#define FAV_LD 136
#define FAP_LD 36
#define FA_QS   0
#define FA_KV0  (64*FAQ_LD)
#define FA_KVST (32*FAK_LD + 32*FAV_LD)
#define FA_PS   (FA_KV0 + 2*FA_KVST)
#define FA_TOT  (FA_PS + 4*16*FAP_LD)
#define ATTN_SCALE 0.08838834764831845f

__global__ void __launch_bounds__(128)
flash_attn_kernel(const float* __restrict__ Q, const float* __restrict__ K,
                  const float* __restrict__ V, float* __restrict__ O)
{
    extern __shared__ uint32_t sh[];
    const int qb   = (gridDim.x - 1) - blockIdx.x;
    const int hh   = blockIdx.y;
    const int tid  = threadIdx.x;
    const int lane = tid & 31;
    const int warp = tid >> 5;
    const int g    = lane >> 2;
    const int tg   = lane & 3;
    const int wm   = warp * 16;
    const int q0   = qb * 64;
    const long long hoff = (long long)hh * HD;

    const uint32_t shbase = (uint32_t)__cvta_generic_to_shared(sh);

    #pragma unroll
    for (int j = 0; j < 16; j++) {
        int idx = tid + 128 * j;
        int r = idx >> 5, c4 = (idx & 31) * 4;
        float4 t = *reinterpret_cast<const float4*>(&Q[(long long)(q0 + r) * H + hoff + c4]);
        uint4 v = make_uint4(f2tf32(t.x * ATTN_SCALE), f2tf32(t.y * ATTN_SCALE),
                             f2tf32(t.z * ATTN_SCALE), f2tf32(t.w * ATTN_SCALE));
        *reinterpret_cast<uint4*>(&sh[FA_QS + r * FAQ_LD + c4]) = v;
    }

    const int ldrow = tid >> 5;
    const int ldc4  = (tid & 31) * 4;

    auto issue_chunk = [&](int c, int s) {
        uint32_t kbase = shbase + (FA_KV0 + s * FA_KVST) * 4;
        uint32_t vbase = kbase + 32 * FAK_LD * 4;
        #pragma unroll
        for (int j = 0; j < 8; j++) {
            int r = ldrow + 4 * j;
            long long gofs = (long long)(c * 32 + r) * H + hoff + ldc4;
            cp_async16(kbase + (r * FAK_LD + ldc4) * 4, &K[gofs]);
            cp_async16(vbase + (r * FAV_LD + ldc4) * 4, &V[gofs]);
        }
        cp_commit();
    };

    float Oacc[16][4];
    #pragma unroll
    for (int nt = 0; nt < 16; nt++)
        #pragma unroll
        for (int c = 0; c < 4; c++) Oacc[nt][c] = 0.f;
    float m0r = -1e30f, m1r = -1e30f, l0r = 0.f, l1r = 0.f;

    uint32_t* Pw = &sh[FA_PS + warp * 16 * FAP_LD];
    const int nc = 2 * qb + 2;

    issue_chunk(0, 0);

    for (int c = 0; c < nc; c++) {
        cp_wait0();
        __syncthreads();
        if (c + 1 < nc) issue_chunk(c + 1, (c + 1) & 1);

        const uint32_t* K_ = &sh[FA_KV0 + (c & 1) * FA_KVST];
        const uint32_t* V_ = K_ + 32 * FAK_LD;

        float Sacc[4][4];
        #pragma unroll
        for (int nt = 0; nt < 4; nt++)
            #pragma unroll
            for (int cc = 0; cc < 4; cc++) Sacc[nt][cc] = 0.f;

        #pragma unroll
        for (int kk = 0; kk < 128; kk += 8) {
            uint32_t a0 = sh[FA_QS + (wm + g) * FAQ_LD + kk + tg];
            uint32_t a1 = sh[FA_QS + (wm + g + 8) * FAQ_LD + kk + tg];
            uint32_t a2 = sh[FA_QS + (wm + g) * FAQ_LD + kk + tg + 4];
            uint32_t a3 = sh[FA_QS + (wm + g + 8) * FAQ_LD + kk + tg + 4];
            #pragma unroll
            for (int nt = 0; nt < 4; nt++) {
                uint32_t b0 = K_[(nt * 8 + g) * FAK_LD + kk + tg];
                uint32_t b1 = K_[(nt * 8 + g) * FAK_LD + kk + tg + 4];
                mma_tf32(Sacc[nt][0], Sacc[nt][1], Sacc[nt][2], Sacc[nt][3],
                         a0, a1, a2, a3, b0, b1);
            }
        }

        if (c >= 2 * qb) {
            int r0g = q0 + wm + g, r1g = r0g + 8;
            #pragma unroll
            for (int nt = 0; nt < 4; nt++) {
                int c0 = c * 32 + nt * 8 + 2 * tg, c1 = c0 + 1;
                if (c0 > r0g) Sacc[nt][0] = -1e30f;
                if (c1 > r0g) Sacc[nt][1] = -1e30f;
                if (c0 > r1g) Sacc[nt][2] = -1e30f;
                if (c1 > r1g) Sacc[nt][3] = -1e30f;
            }
        }

        float rmax0 = -1e30f, rmax1 = -1e30f;
        #pragma unroll
        for (int nt = 0; nt < 4; nt++) {
            rmax0 = fmaxf(rmax0, fmaxf(Sacc[nt][0], Sacc[nt][1]));
            rmax1 = fmaxf(rmax1, fmaxf(Sacc[nt][2], Sacc[nt][3]));
        }
        rmax0 = fmaxf(rmax0, __shfl_xor_sync(0xffffffffu, rmax0, 1));
        rmax0 = fmaxf(rmax0, __shfl_xor_sync(0xffffffffu, rmax0, 2));
        rmax1 = fmaxf(rmax1, __shfl_xor_sync(0xffffffffu, rmax1, 1));
        rmax1 = fmaxf(rmax1, __shfl_xor_sync(0xffffffffu, rmax1, 2));

        float nm0 = fmaxf(m0r, rmax0), nm1 = fmaxf(m1r, rmax1);
        float al0 = __expf(m0r - nm0), al1 = __expf(m1r - nm1);
        float sum0 = 0.f, sum1 = 0.f;
        #pragma unroll
        for (int nt = 0; nt < 4; nt++) {
            float p00 = __expf(Sacc[nt][0] - nm0);
            float p01 = __expf(Sacc[nt][1] - nm0);
            float p10 = __expf(Sacc[nt][2] - nm1);
            float p11 = __expf(Sacc[nt][3] - nm1);
            sum0 += p00 + p01; sum1 += p10 + p11;
            int cl = nt * 8 + 2 * tg;
            Pw[g * FAP_LD + cl]           = f2tf32(p00);
            Pw[g * FAP_LD + cl + 1]       = f2tf32(p01);
            Pw[(g + 8) * FAP_LD + cl]     = f2tf32(p10);
            Pw[(g + 8) * FAP_LD + cl + 1] = f2tf32(p11);
        }
        sum0 += __shfl_xor_sync(0xffffffffu, sum0, 1);
        sum0 += __shfl_xor_sync(0xffffffffu, sum0, 2);
        sum1 += __shfl_xor_sync(0xffffffffu, sum1, 1);
        sum1 += __shfl_xor_sync(0xffffffffu, sum1, 2);
        l0r = l0r * al0 + sum0;
        l1r = l1r * al1 + sum1;
        m0r = nm0; m1r = nm1;

        #pragma unroll
        for (int nt = 0; nt < 16; nt++) {
            Oacc[nt][0] *= al0; Oacc[nt][1] *= al0;
            Oacc[nt][2] *= al1; Oacc[nt][3] *= al1;
        }

        __syncwarp();

        #pragma unroll
        for (int kk = 0; kk < 32; kk += 8) {
            uint32_t a0 = Pw[g * FAP_LD + kk + tg];
            uint32_t a1 = Pw[(g + 8) * FAP_LD + kk + tg];
            uint32_t a2 = Pw[g * FAP_LD + kk + tg + 4];
            uint32_t a3 = Pw[(g + 8) * FAP_LD + kk + tg + 4];
            #pragma unroll
            for (int nt = 0; nt < 16; nt++) {
                uint32_t b0 = V_[(kk + tg) * FAV_LD + nt * 8 + g];
                uint32_t b1 = V_[(kk + tg + 4) * FAV_LD + nt * 8 + g];
                mma_tf32(Oacc[nt][0], Oacc[nt][1], Oacc[nt][2], Oacc[nt][3],
                         a0, a1, a2, a3, b0, b1);
            }
        }
    }

    float inv0 = 1.f / l0r, inv1 = 1.f / l1r;
    long long r0 = q0 + wm + g, r1 = r0 + 8;
    #pragma unroll
    for (int nt = 0; nt < 16; nt++) {
        int c = nt * 8 + 2 * tg;
        *reinterpret_cast<float2*>(&O[r0 * H + hoff + c]) =
            make_float2(Oacc[nt][0] * inv0, Oacc[nt][1] * inv0);
        *reinterpret_cast<float2*>(&O[r1 * H + hoff + c]) =
            make_float2(Oacc[nt][2] * inv1, Oacc[nt][3] * inv1);
    }
}

// ---------------- elementwise / norm ----------------
__global__ void rmsnorm_kernel(const float* __restrict__ x, const float* __restrict__ w,
                               float* __restrict__ y) {
    int t = blockIdx.x;
    const float4* xr = reinterpret_cast<const float4*>(x + (long long)t * H);
    const float4* w4 = reinterpret_cast<const float4*>(w);
    float4* yr = reinterpret_cast<float4*>(y + (long long)t * H);
    float s = 0.f;
    for (int i = threadIdx.x; i < H / 4; i += blockDim.x) {
        float4 v = xr[i];
        s += v.x * v.x + v.y * v.y + v.z * v.z + v.w * v.w;
    }
    s = blockReduceSum(s);
    float scale = rsqrtf(s / (float)H + EPS);
    for (int i = threadIdx.x; i < H / 4; i += blockDim.x) {
        float4 v = xr[i], ww = w4[i];
        yr[i] = make_float4(v.x * scale * ww.x, v.y * scale * ww.y,
                            v.z * scale * ww.z, v.w * scale * ww.w);
    }
}

// merged silu*mul: grid (S, 20)
__global__ void silumul_all_kernel(float4* __restrict__ gbuf, const float4* __restrict__ ubuf,
                                   float* __restrict__ gs, const float* __restrict__ us,
                                   const int* __restrict__ cnt)
{
    int e = blockIdx.y, slot = blockIdx.x;
    float4* gp; const float4* up;
    if (e < E) {
        if (slot >= cnt[e]) return;
        long long base = ((long long)e * S + slot) * (IM / 4);
        gp = gbuf + base;
        up = ubuf + base;
    } else {
        long long off = (long long)slot * IS + (e - E) * 1408;
        gp = reinterpret_cast<float4*>(gs + off);
        up = reinterpret_cast<const float4*>(us + off);
    }
    for (int i = threadIdx.x; i < IM / 4; i += blockDim.x) {
        float4 x = gp[i], y = up[i];
        x.x = (x.x / (1.f + __expf(-x.x))) * y.x;
        x.y = (x.y / (1.f + __expf(-x.y))) * y.y;
        x.z = (x.z / (1.f + __expf(-x.z))) * y.z;
        x.w = (x.w / (1.f + __expf(-x.w))) * y.w;
        gp[i] = x;
    }
}

// ---------------- MoE routing ----------------
__global__ void routing_kernel(const float* __restrict__ logits, int* __restrict__ cnt,
                               int* __restrict__ tke, int* __restrict__ tks,
                               float* __restrict__ tkw, int* __restrict__ tok) {
    int t = blockIdx.x * blockDim.x + threadIdx.x;
    if (t >= S) return;
    float p[E];
    float mx = -3.4e38f;
    #pragma unroll
    for (int e = 0; e < E; e++) { p[e] = logits[t * E + e]; mx = fmaxf(mx, p[e]); }
    float sum = 0.f;
    #pragma unroll
    for (int e = 0; e < E; e++) { p[e] = __expf(p[e] - mx); sum += p[e]; }
    float inv = 1.f / sum;
    #pragma unroll
    for (int e = 0; e < E; e++) p[e] *= inv;
    int ids[TOPK]; float ws[TOPK]; float wsum = 0.f;
    #pragma unroll
    for (int k = 0; k < TOPK; k++) {
        float bv = -1.f; int bi = 0;
        #pragma unroll
        for (int e = 0; e < E; e++) if (p[e] > bv) { bv = p[e]; bi = e; }
        ids[k] = bi; ws[k] = bv; wsum += bv; p[bi] = -2.f;
    }
    float wi = 1.f / wsum;
    #pragma unroll
    for (int k = 0; k < TOPK; k++) {
        int slot = atomicAdd(&cnt[ids[k]], 1);
        tke[t * TOPK + k] = ids[k];
        tks[t * TOPK + k] = slot;
        tkw[t * TOPK + k] = ws[k] * wi;
        tok[ids[k] * S + slot] = t;
    }
}

// fused combine: shared = sum of 4 down-partial slabs (in part); out = sg*shared + Σ w*y
__global__ void combine_kernel(const float* __restrict__ P, const float* __restrict__ sg,
                               const float* __restrict__ ybuf,
                               const int* __restrict__ tke, const int* __restrict__ tks,
                               const float* __restrict__ tkw, float* __restrict__ out) {
    const long long SH = (long long)S * H;
    int t = blockIdx.x;
    float gg = sg[t];
    int e0 = tke[t*4+0], e1 = tke[t*4+1], e2 = tke[t*4+2], e3 = tke[t*4+3];
    int s0 = tks[t*4+0], s1 = tks[t*4+1], s2 = tks[t*4+2], s3 = tks[t*4+3];
    float w0 = tkw[t*4+0], w1 = tkw[t*4+1], w2 = tkw[t*4+2], w3 = tkw[t*4+3];
    const float4* y0 = reinterpret_cast<const float4*>(ybuf + ((long long)e0 * S + s0) * H);
    const float4* y1 = reinterpret_cast<const float4*>(ybuf + ((long long)e1 * S + s1) * H);
    const float4* y2 = reinterpret_cast<const float4*>(ybuf + ((long long)e2 * S + s2) * H);
    const float4* y3 = reinterpret_cast<const float4*>(ybuf + ((long long)e3 * S + s3) * H);
    const long long rowb = (long long)t * H;
    float4* o = reinterpret_cast<float4*>(out + rowb);
    for (int i = threadIdx.x; i < H / 4; i += blockDim.x) {
        int c = i * 4;
        float4 p0 = *reinterpret_cast<const float4*>(P + rowb + c);
        float4 p1 = *reinterpret_cast<const float4*>(P + SH + rowb + c);
        float4 p2 = *reinterpret_cast<const float4*>(P + 2 * SH + rowb + c);
        float4 p3 = *reinterpret_cast<const float4*>(P + 3 * SH + rowb + c);
        float4 a = make_float4(p0.x + p1.x + p2.x + p3.x, p0.y + p1.y + p2.y + p3.y,
                               p0.z + p1.z + p2.z + p3.z, p0.w + p1.w + p2.w + p3.w);
        float4 b0 = y0[i], b1 = y1[i], b2 = y2[i], b3 = y3[i];
        o[i] = make_float4(
            gg * a.x + w0 * b0.x + w1 * b1.x + w2 * b2.x + w3 * b3.x,
            gg * a.y + w0 * b0.y + w1 * b1.y + w2 * b2.y + w3 * b3.y,
            gg * a.z + w0 * b0.z + w1 * b1.z + w2 * b2.z + w3 * b3.z,
            gg * a.w + w0 * b0.w + w1 * b1.w + w2 * b2.w + w3 * b3.w);
    }
}

// ---------------- host orchestration ----------------
static inline void gemm_ext(const float* A, const GSets& sets, int nsets,
                            int M, int N, int K, int lda, int ldb, int ldc,
                            long long sA, long long sB, long long sC,
                            float alpha, int transB, const int* mcnt, int inner,
                            int nsplit, int ksz, float* part, const int* rowidx,
                            int inner1, int Malt,
                            const float* A2, int lda2, long long aSlice,
                            int ldb2, long long bSlice, int ldc2, long long cSlice,
                            int maxMtiles) {
    dim3 grid((N + 127) / 128, maxMtiles, nsets * inner * nsplit);
    tgemm_kernel<<<grid, 128>>>(A, sets, M, N, K, lda, ldb, ldc, sA, sB, sC,
                                alpha, transB, mcnt, inner, nsplit, ksz, part, rowidx,
                                inner1, Malt, A2, lda2, aSlice, ldb2, bSlice, ldc2, cSlice);
}

static inline void gemm_multi(const float* A, const GSets& sets, int nsets,
                              int M, int N, int K, int lda, int ldb, int ldc,
                              long long sA, long long sB, long long sC,
                              float alpha, int transB, const int* mcnt, int inner,
                              int nsplit = 1, int ksz = 0, float* part = nullptr,
                              const int* rowidx = nullptr) {
    gemm_ext(A, sets, nsets, M, N, K, lda, ldb, ldc, sA, sB, sC, alpha, transB,
             mcnt, inner, nsplit, ksz, part, rowidx,
             inner, 0, nullptr, 0, 0, 0, 0, 0, 0, (M + 127) / 128);
}

extern "C" void kernel_launch(void* const* d_in, const int* in_sizes, int n_in,
                              void* d_out, int out_size) {
    const int*   positions = (const int*)  d_in[0];
    const float* hidden    = (const float*)d_in[1];
    const float* ln1       = (const float*)d_in[2];
    const float* ln2       = (const float*)d_in[3];
    const float* q_w       = (const float*)d_in[4];
    const float* q_b       = (const float*)d_in[5];
    const float* k_w       = (const float*)d_in[6];
    const float* k_b       = (const float*)d_in[7];
    const float* v_w       = (const float*)d_in[8];
    const float* v_b       = (const float*)d_in[9];
    const float* o_w       = (const float*)d_in[10];
    const float* router_w  = (const float*)d_in[11];
    const float* we_gate   = (const float*)d_in[12];
    const float* we_up     = (const float*)d_in[13];
    const float* we_down   = (const float*)d_in[14];
    const float* ws_gate   = (const float*)d_in[15];
    const float* ws_up     = (const float*)d_in[16];
    const float* ws_down   = (const float*)d_in[17];
    const float* wsg       = (const float*)d_in[18];
    float* out = (float*)d_out;

    float *h1, *q, *k, *v, *attn, *h2, *gs, *us;
    float *logits, *sgv, *gbuf, *ubuf, *ybuf, *tkw, *part;
    int *cnt, *tke, *tks, *tok;
    cudaGetSymbolAddress((void**)&h1,     g_h1);
    cudaGetSymbolAddress((void**)&q,      g_q);
    cudaGetSymbolAddress((void**)&k,      g_k);
    cudaGetSymbolAddress((void**)&v,      g_v);
    cudaGetSymbolAddress((void**)&attn,   g_attn);
    cudaGetSymbolAddress((void**)&h2,     g_h2);
    cudaGetSymbolAddress((void**)&gs,     g_gs);
    cudaGetSymbolAddress((void**)&us,     g_us);
    cudaGetSymbolAddress((void**)&logits, g_logits);
    cudaGetSymbolAddress((void**)&sgv,    g_sg);
    cudaGetSymbolAddress((void**)&cnt,    g_cnt);
    cudaGetSymbolAddress((void**)&tke,    g_tk_e);
    cudaGetSymbolAddress((void**)&tks,    g_tk_slot);
    cudaGetSymbolAddress((void**)&tkw,    g_tk_w);
    cudaGetSymbolAddress((void**)&tok,    g_tok);
    cudaGetSymbolAddress((void**)&gbuf,   g_gbuf);
    cudaGetSymbolAddress((void**)&ubuf,   g_ubuf);
    cudaGetSymbolAddress((void**)&ybuf,   g_ybuf);
    cudaGetSymbolAddress((void**)&part,   g_part);

    cudaFuncSetAttribute(flash_attn_kernel,
                         cudaFuncAttributeMaxDynamicSharedMemorySize, FA_TOT * 4);

    // --- pre-attention norm + fused QKV (split-K 3) + fused bias/RoPE reduce ---
    rmsnorm_kernel<<<S, 256>>>(hidden, ln1, h1);
    {
        GSets s{};
        s.s[0] = {q_w, nullptr, nullptr, nullptr, nullptr};
        s.s[1] = {k_w, nullptr, nullptr, nullptr, nullptr};
        s.s[2] = {v_w, nullptr, nullptr, nullptr, nullptr};
        gemm_multi(h1, s, 3, S, H, H, H, H, H, 0, 0, 0, 1.f, 0, nullptr, 1,
                   3, 688, part);
        reduce_qkv_rope_kernel<<<S, 256>>>(part, q, k, v, q_b, k_b, v_b, positions);
    }

    // --- fused flash attention ---
    flash_attn_kernel<<<dim3(S / 64, NH), 128, FA_TOT * 4>>>(q, k, v, attn);

    // --- O proj (split-K 4) + fused residual/rmsnorm/sgate ---
    {
        GSets s{};
        s.s[0] = {o_w, nullptr, nullptr, nullptr, nullptr};
        gemm_multi(attn, s, 1, S, H, H, H, H, 0, 0, 0, 0,
                   1.f, 0, nullptr, 1, 4, 512, part);
        oproj_rms_sgate_kernel<<<S, 256>>>(part, hidden, ln2, wsg, h2, sgv);
    }

    // --- router (split-K 8) + dispatch ---
    {
        GSets s{};
        s.s[0] = {router_w, nullptr, nullptr, nullptr, nullptr};
        gemm_multi(h2, s, 1, S, E, H, H, E, E, 0, 0, 0,
                   1.f, 0, nullptr, 1, 8, 256, part);
        reduce_logits_zero_kernel<<<(S * E / 4 + 255) / 256, 256>>>(
            (const float4*)part, (float4*)logits, cnt,
            8, (long long)S * E / 4, (long long)S * E / 4);
    }
    routing_kernel<<<(S + 255) / 256, 256>>>(logits, cnt, tke, tks, tkw, tok);

    // --- MERGED gate/up: 16 routed experts + 4 shared-expert N-slices ---
    {
        GSets s{};
        s.s[0] = {we_gate, gbuf, nullptr, ws_gate, gs};
        s.s[1] = {we_up,   ubuf, nullptr, ws_up,   us};
        gemm_ext(h2, s, 2, S, IM, H, H, IM, IM,
                 0, (long long)H * IM, (long long)S * IM,
                 1.f, 0, cnt, 20, 1, 0, nullptr, tok,
                 16, S, h2, H, 0, IS, 1408, IS, 1408, S / 128);
    }
    silumul_all_kernel<<<dim3(S, 20), 256>>>((float4*)gbuf, (const float4*)ubuf,
                                             gs, us, cnt);

    // --- MERGED down: 16 routed experts + 4 shared-expert K-slices (partials) ---
    {
        GSets s{};
        s.s[0] = {we_down, ybuf, nullptr, ws_down, part};
        gemm_ext(gbuf, s, 1, S, H, IM, IM, H, H,
                 (long long)S * IM, (long long)IM * H, (long long)S * H,
                 1.f, 0, cnt, 20, 1, 0, nullptr, nullptr,
                 16, S, gs, IS, 1408, H, (long long)1408 * H, H, (long long)S * H,
                 S / 128);
    }

    // --- final combine (sums shared-expert partials inline) ---
    combine_kernel<<<S, 256>>>(part, sgv, ybuf, tke, tks, tkw, out);
}

// round 17
// speedup vs baseline: 2.4345x; 1.0065x over previous
#include <cuda_runtime.h>
#include <math.h>
#include <stdint.h>

#define S   1024
#define H   2048
#define NH  16
#define HD  128
#define E   16
#define TOPK 4
#define IM  1408
#define IS  5632
#define EPS 1e-6f

// ---------------- scratch (device globals) ----------------
__device__ float g_h1[S*H];
__device__ float g_q[S*H];
__device__ float g_k[S*H];
__device__ float g_v[S*H];
__device__ float g_attn[S*H];
__device__ float g_h2[S*H];
__device__ float g_gs[S*IS];
__device__ float g_us[S*IS];
__device__ float g_logits[S*E];
__device__ float g_sg[S];
__device__ int   g_cnt[E];
__device__ int   g_tk_e[S*TOPK];
__device__ int   g_tk_slot[S*TOPK];
__device__ float g_tk_w[S*TOPK];
__device__ int   g_tok[E*S];
__device__ float g_gbuf[E*S*IM];
__device__ float g_ubuf[E*S*IM];
__device__ float g_ybuf[E*S*H];
__device__ float g_part[18874368];   // up to 9 S*H slabs (75 MB)

// ---------------- block reductions ----------------
__device__ __forceinline__ float blockReduceSum(float v) {
    __shared__ float sh[33];
    int lane = threadIdx.x & 31, wid = threadIdx.x >> 5;
    #pragma unroll
    for (int o = 16; o; o >>= 1) v += __shfl_down_sync(0xffffffffu, v, o);
    if (lane == 0) sh[wid] = v;
    __syncthreads();
    int nw = (blockDim.x + 31) >> 5;
    float t = (threadIdx.x < nw) ? sh[threadIdx.x] : 0.f;
    if (wid == 0) {
        #pragma unroll
        for (int o = 16; o; o >>= 1) t += __shfl_down_sync(0xffffffffu, t, o);
        if (lane == 0) sh[32] = t;
    }
    __syncthreads();
    float r = sh[32];
    __syncthreads();
    return r;
}

// ---------------- tf32 helpers ----------------
__device__ __forceinline__ uint32_t f2tf32(float f) {
    uint32_t r;
    asm("cvt.rna.tf32.f32 %0, %1;" : "=r"(r) : "f"(f));
    return r;
}

__device__ __forceinline__ void mma_tf32(float& d0, float& d1, float& d2, float& d3,
                                         uint32_t a0, uint32_t a1, uint32_t a2, uint32_t a3,
                                         uint32_t b0, uint32_t b1) {
    asm volatile(
        "mma.sync.aligned.m16n8k8.row.col.f32.tf32.tf32.f32 "
        "{%0,%1,%2,%3}, {%4,%5,%6,%7}, {%8,%9}, {%0,%1,%2,%3};"
        : "+f"(d0), "+f"(d1), "+f"(d2), "+f"(d3)
        : "r"(a0), "r"(a1), "r"(a2), "r"(a3), "r"(b0), "r"(b1));
}

__device__ __forceinline__ void cp_async16(uint32_t smem_addr, const void* gptr) {
    asm volatile("cp.async.cg.shared.global [%0], [%1], 16;"
                 :: "r"(smem_addr), "l"(gptr));
}
__device__ __forceinline__ void cp_commit() {
    asm volatile("cp.async.commit_group;" ::: "memory");
}
__device__ __forceinline__ void cp_wait0() {
    asm volatile("cp.async.wait_group 0;" ::: "memory");
}

// ---------------- TF32 GEMM (BK=16, 128 threads, 64x64 warp tiles) ----------------
#define LDA_SH 20
#define LDB_SH 136
#define STG_SZ (128 * LDA_SH)

struct GSet { const float* B; float* C; const float* bias; const float* B2; float* C2; };
struct GSets { GSet s[3]; };

__device__ __forceinline__ void stage_load(
    float4* avr, float4* bvr,
    const float* const* aRowP, const float* const* bRowP, const float* bCol,
    int kt, int ldb, int transB, int acq, int brow)
{
    const float4 zf4 = make_float4(0.f, 0.f, 0.f, 0.f);
    #pragma unroll
    for (int p = 0; p < 4; p++)
        avr[p] = aRowP[p] ? *reinterpret_cast<const float4*>(aRowP[p] + kt + acq) : zf4;
    if (!transB) {
        #pragma unroll
        for (int p = 0; p < 4; p++)
            bvr[p] = bCol ? *reinterpret_cast<const float4*>(bCol + (long long)(kt + brow + 4 * p) * ldb) : zf4;
    } else {
        #pragma unroll
        for (int p = 0; p < 4; p++)
            bvr[p] = bRowP[p] ? *reinterpret_cast<const float4*>(bRowP[p] + kt + acq) : zf4;
    }
}

__device__ __forceinline__ void stage_store(
    uint32_t* As, uint32_t* Bs, const float4* avr, const float4* bvr,
    int transB, int arow, int acq, int brow, int bn4)
{
    #pragma unroll
    for (int p = 0; p < 4; p++) {
        int r = arow + p * 32;
        uint4 v = make_uint4(f2tf32(avr[p].x), f2tf32(avr[p].y),
                             f2tf32(avr[p].z), f2tf32(avr[p].w));
        *reinterpret_cast<uint4*>(&As[r * LDA_SH + acq]) = v;
    }
    if (!transB) {
        #pragma unroll
        for (int p = 0; p < 4; p++) {
            int k = brow + p * 4;
            uint4 v = make_uint4(f2tf32(bvr[p].x), f2tf32(bvr[p].y),
                                 f2tf32(bvr[p].z), f2tf32(bvr[p].w));
            *reinterpret_cast<uint4*>(&Bs[k * LDB_SH + bn4]) = v;
        }
    } else {
        #pragma unroll
        for (int p = 0; p < 4; p++) {
            int r = arow + p * 32;
            uint4 v = make_uint4(f2tf32(bvr[p].x), f2tf32(bvr[p].y),
                                 f2tf32(bvr[p].z), f2tf32(bvr[p].w));
            *reinterpret_cast<uint4*>(&Bs[r * LDA_SH + acq]) = v;
        }
    }
}

// split-K partial layout (primary batches): part + ((set*inner+ib)*nsplit+sp)*(Mfull*N)
__global__ void __launch_bounds__(128, 2)
tgemm_kernel(const float* __restrict__ A, GSets sets,
             int M, int N, int K, int lda, int ldb, int ldc,
             long long sA, long long sB, long long sC,
             float alpha, int transB, const int* __restrict__ mcnt,
             int inner, int nsplit, int ksz,
             float* __restrict__ part,
             const int* __restrict__ rowidx_all,
             int inner1, int Malt,
             const float* __restrict__ A2, int lda2, long long aSlice,
             int ldb2, long long bSlice, int ldc2, long long cSlice)
{
    const int z = blockIdx.z;
    const int sp  = z % nsplit;
    const int t   = z / nsplit;
    const int ib  = t % inner;
    const int set = t / inner;
    const bool alt = (ib >= inner1);

    const int Mfull = M;
    if (alt) M = Malt;
    else if (mcnt) M = mcnt[ib];
    const int m0 = blockIdx.y * 128;
    if (m0 >= M) return;
    const int n0 = blockIdx.x * 128;

    const float* Ab;  int ldaE, ldbE;
    const float* Bb;
    const float* bias;
    const int* rowidx;
    float* Cb;
    int ldcc;
    if (!alt) {
        Ab = A + (long long)ib * sA;            ldaE = lda;
        Bb = sets.s[set].B + (long long)ib * sB; ldbE = ldb;
        bias = sets.s[set].bias;
        rowidx = rowidx_all ? rowidx_all + (long long)ib * S : nullptr;
        if (nsplit > 1) {
            Cb = part + (((long long)set * inner + ib) * nsplit + sp) * ((long long)Mfull * N);
            ldcc = N;
            bias = nullptr;
        } else {
            Cb = sets.s[set].C + (long long)ib * sC;
            ldcc = ldc;
        }
    } else {
        int sl = ib - inner1;
        Ab = A2 + (long long)sl * aSlice;             ldaE = lda2;
        Bb = sets.s[set].B2 + (long long)sl * bSlice; ldbE = ldb2;
        Cb = sets.s[set].C2 + (long long)sl * cSlice;
        ldcc = ldc2;
        bias = nullptr;
        rowidx = nullptr;
    }

    int kbeg = (!alt && nsplit > 1) ? sp * ksz : 0;
    int kend = (!alt && nsplit > 1) ? kbeg + ksz : K;
    if (kend > K) kend = K;

    __shared__ uint32_t As[2][STG_SZ];
    __shared__ uint32_t Bs[2][STG_SZ];

    const int tid  = threadIdx.x;
    const int lane = tid & 31;
    const int warp = tid >> 5;
    const int wm   = (warp & 1) * 64;
    const int wn   = (warp >> 1) * 64;
    const int g    = lane >> 2;
    const int tg   = lane & 3;

    const int arow = tid >> 2;
    const int acq  = (tid & 3) * 4;
    const int brow = tid >> 5;
    const int bn4  = (tid & 31) * 4;

    const float* aRowP[4];
    #pragma unroll
    for (int p = 0; p < 4; p++) {
        int r = m0 + arow + p * 32;
        if (r < M) {
            long long gr = rowidx ? (long long)rowidx[r] : (long long)r;
            aRowP[p] = Ab + gr * ldaE;
        } else aRowP[p] = nullptr;
    }
    const float* bRowP[4] = {nullptr, nullptr, nullptr, nullptr};
    const float* bCol = nullptr;
    if (!transB) {
        if (n0 + bn4 < N) bCol = Bb + n0 + bn4;
    } else {
        #pragma unroll
        for (int p = 0; p < 4; p++) {
            int r = n0 + arow + p * 32;
            if (r < N) bRowP[p] = Bb + (long long)r * ldbE;
        }
    }

    float acc[4][8][4];
    #pragma unroll
    for (int i = 0; i < 4; i++)
        #pragma unroll
        for (int j = 0; j < 8; j++)
            #pragma unroll
            for (int c = 0; c < 4; c++) acc[i][j][c] = 0.f;

    float4 avr[4], bvr[4];

    stage_load(avr, bvr, aRowP, bRowP, bCol, kbeg, ldbE, transB, acq, brow);
    stage_store(As[0], Bs[0], avr, bvr, transB, arow, acq, brow, bn4);
    __syncthreads();

    int p = 0;
    for (int kt = kbeg; kt < kend; kt += 16) {
        const bool has_next = (kt + 16 < kend);
        if (has_next)
            stage_load(avr, bvr, aRowP, bRowP, bCol, kt + 16, ldbE, transB, acq, brow);

        const uint32_t* Asp = As[p];
        const uint32_t* Bsp = Bs[p];
        #pragma unroll
        for (int kk = 0; kk < 16; kk += 8) {
            uint32_t af[4][4];
            #pragma unroll
            for (int mt = 0; mt < 4; mt++) {
                const uint32_t* base = &Asp[(wm + mt * 16 + g) * LDA_SH + kk + tg];
                af[mt][0] = base[0];
                af[mt][1] = base[8 * LDA_SH];
                af[mt][2] = base[4];
                af[mt][3] = base[8 * LDA_SH + 4];
            }
            uint32_t bf[8][2];
            if (!transB) {
                #pragma unroll
                for (int nt = 0; nt < 8; nt++) {
                    int n = wn + nt * 8 + g;
                    bf[nt][0] = Bsp[(kk + tg) * LDB_SH + n];
                    bf[nt][1] = Bsp[(kk + tg + 4) * LDB_SH + n];
                }
            } else {
                #pragma unroll
                for (int nt = 0; nt < 8; nt++) {
                    int n = wn + nt * 8 + g;
                    bf[nt][0] = Bsp[n * LDA_SH + kk + tg];
                    bf[nt][1] = Bsp[n * LDA_SH + kk + tg + 4];
                }
            }
            #pragma unroll
            for (int mt = 0; mt < 4; mt++)
                #pragma unroll
                for (int nt = 0; nt < 8; nt++)
                    mma_tf32(acc[mt][nt][0], acc[mt][nt][1], acc[mt][nt][2], acc[mt][nt][3],
                             af[mt][0], af[mt][1], af[mt][2], af[mt][3],
                             bf[nt][0], bf[nt][1]);
        }

        if (has_next) {
            stage_store(As[1 - p], Bs[1 - p], avr, bvr, transB, arow, acq, brow, bn4);
            __syncthreads();
            p ^= 1;
        }
    }

    #pragma unroll
    for (int mt = 0; mt < 4; mt++) {
        int r0 = m0 + wm + mt * 16 + g;
        int r1 = r0 + 8;
        #pragma unroll
        for (int nt = 0; nt < 8; nt++) {
            int col = n0 + wn + nt * 8 + 2 * tg;
            if (col >= N) continue;
            float b0 = bias ? bias[col]     : 0.f;
            float b1 = bias ? bias[col + 1] : 0.f;
            if (r0 < M) {
                float2 v = make_float2(acc[mt][nt][0] * alpha + b0,
                                       acc[mt][nt][1] * alpha + b1);
                *reinterpret_cast<float2*>(&Cb[(long long)r0 * ldcc + col]) = v;
            }
            if (r1 < M) {
                float2 v = make_float2(acc[mt][nt][2] * alpha + b0,
                                       acc[mt][nt][3] * alpha + b1);
                *reinterpret_cast<float2*>(&Cb[(long long)r1 * ldcc + col]) = v;
            }
        }
    }
}

// logits split-K reduce + zero cnt
__global__ void reduce_logits_zero_kernel(const float4* __restrict__ P,
                                          float4* __restrict__ C, int* __restrict__ cnt,
                                          int nsplit, long long sSplit4, long long total4)
{
    long long i = (long long)blockIdx.x * blockDim.x + threadIdx.x;
    if (blockIdx.x == 0 && threadIdx.x < E) cnt[threadIdx.x] = 0;
    if (i >= total4) return;
    float4 s = P[i];
    for (int sp = 1; sp < nsplit; sp++) {
        float4 t = P[sp * sSplit4 + i];
        s.x += t.x; s.y += t.y; s.z += t.z; s.w += t.w;
    }
    C[i] = s;
}

// QKV split-K reduce with fused bias + RoPE (3 splits). Grid: S x 256.
__global__ void reduce_qkv_rope_kernel(const float* __restrict__ P,
                                       float* __restrict__ q, float* __restrict__ k,
                                       float* __restrict__ v,
                                       const float* __restrict__ qb,
                                       const float* __restrict__ kb,
                                       const float* __restrict__ vb,
                                       const int* __restrict__ pos)
{
    const long long SH = (long long)S * H;
    const int t = blockIdx.x;
    const int tid = threadIdx.x;
    const int h  = tid >> 4;
    const int d4 = (tid & 15) * 4;
    const long long rowb = (long long)t * H;
    const int cb = h * HD + d4;
    float p = (float)pos[t];

    float cs[4], sn[4];
    #pragma unroll
    for (int j = 0; j < 4; j++) {
        float inv = exp2f(-(float)(d4 + j) * 0.31143075889569023f);
        sincosf(p * inv, &sn[j], &cs[j]);
    }

    #pragma unroll
    for (int set = 0; set < 2; set++) {
        const float* P0 = P + ((long long)set * 3 + 0) * SH + rowb;
        const float* P1 = P + ((long long)set * 3 + 1) * SH + rowb;
        const float* P2 = P + ((long long)set * 3 + 2) * SH + rowb;
        const float* bias = set ? kb : qb;
        float* dst = set ? k : q;
        float4 a0 = *reinterpret_cast<const float4*>(P0 + cb);
        float4 a1 = *reinterpret_cast<const float4*>(P1 + cb);
        float4 a2 = *reinterpret_cast<const float4*>(P2 + cb);
        float4 b0 = *reinterpret_cast<const float4*>(P0 + cb + 64);
        float4 b1 = *reinterpret_cast<const float4*>(P1 + cb + 64);
        float4 b2 = *reinterpret_cast<const float4*>(P2 + cb + 64);
        float4 bi0 = *reinterpret_cast<const float4*>(bias + cb);
        float4 bi1 = *reinterpret_cast<const float4*>(bias + cb + 64);
        float x1[4] = {a0.x + a1.x + a2.x + bi0.x, a0.y + a1.y + a2.y + bi0.y,
                       a0.z + a1.z + a2.z + bi0.z, a0.w + a1.w + a2.w + bi0.w};
        float x2[4] = {b0.x + b1.x + b2.x + bi1.x, b0.y + b1.y + b2.y + bi1.y,
                       b0.z + b1.z + b2.z + bi1.z, b0.w + b1.w + b2.w + bi1.w};
        float4 o1, o2;
        o1.x = x1[0] * cs[0] - x2[0] * sn[0];  o2.x = x2[0] * cs[0] + x1[0] * sn[0];
        o1.y = x1[1] * cs[1] - x2[1] * sn[1];  o2.y = x2[1] * cs[1] + x1[1] * sn[1];
        o1.z = x1[2] * cs[2] - x2[2] * sn[2];  o2.z = x2[2] * cs[2] + x1[2] * sn[2];
        o1.w = x1[3] * cs[3] - x2[3] * sn[3];  o2.w = x2[3] * cs[3] + x1[3] * sn[3];
        *reinterpret_cast<float4*>(dst + rowb + cb)      = o1;
        *reinterpret_cast<float4*>(dst + rowb + cb + 64) = o2;
    }

    {
        const float* P0 = P + 6 * SH + rowb;
        const float* P1 = P + 7 * SH + rowb;
        const float* P2 = P + 8 * SH + rowb;
        #pragma unroll
        for (int r = 0; r < 2; r++) {
            int col = (tid + r * 256) * 4;
            float4 a = *reinterpret_cast<const float4*>(P0 + col);
            float4 b = *reinterpret_cast<const float4*>(P1 + col);
            float4 c = *reinterpret_cast<const float4*>(P2 + col);
            float4 bi = *reinterpret_cast<const float4*>(vb + col);
            *reinterpret_cast<float4*>(v + rowb + col) =
                make_float4(a.x + b.x + c.x + bi.x, a.y + b.y + c.y + bi.y,
                            a.z + b.z + c.z + bi.z, a.w + b.w + c.w + bi.w);
        }
    }
}

// fused: x2 = sum4(Oproj partials) + hidden; h2 = rmsnorm(x2)*ln2w; sg = sigmoid(h2 . wsg)
__global__ void oproj_rms_sgate_kernel(const float* __restrict__ P,
                                       const float* __restrict__ hidden,
                                       const float* __restrict__ w,
                                       const float* __restrict__ wsg,
                                       float* __restrict__ h2, float* __restrict__ sg)
{
    __shared__ float row[H];
    const long long SH = (long long)S * H;
    int t = blockIdx.x;
    const long long rowb = (long long)t * H;
    float s = 0.f;
    for (int i = threadIdx.x; i < H / 4; i += blockDim.x) {
        int c = i * 4;
        float4 a = *reinterpret_cast<const float4*>(P + rowb + c);
        float4 b = *reinterpret_cast<const float4*>(P + SH + rowb + c);
        float4 d = *reinterpret_cast<const float4*>(P + 2 * SH + rowb + c);
        float4 e = *reinterpret_cast<const float4*>(P + 3 * SH + rowb + c);
        float4 hd = *reinterpret_cast<const float4*>(hidden + rowb + c);
        float4 x = make_float4(a.x + b.x + d.x + e.x + hd.x,
                               a.y + b.y + d.y + e.y + hd.y,
                               a.z + b.z + d.z + e.z + hd.z,
                               a.w + b.w + d.w + e.w + hd.w);
        *reinterpret_cast<float4*>(&row[c]) = x;
        s += x.x * x.x + x.y * x.y + x.z * x.z + x.w * x.w;
    }
    s = blockReduceSum(s);
    float scale = rsqrtf(s / (float)H + EPS);
    float d = 0.f;
    for (int i = threadIdx.x; i < H / 4; i += blockDim.x) {
        int c = i * 4;
        float4 x = *reinterpret_cast<const float4*>(&row[c]);
        float4 ww = *reinterpret_cast<const float4*>(w + c);
        float4 gg = *reinterpret_cast<const float4*>(wsg + c);
        float4 o = make_float4(x.x * scale * ww.x, x.y * scale * ww.y,
                               x.z * scale * ww.z, x.w * scale * ww.w);
        *reinterpret_cast<float4*>(h2 + rowb + c) = o;
        d += o.x * gg.x + o.y * gg.y + o.z * gg.z + o.w * gg.w;
    }
    d = blockReduceSum(d);
    if (threadIdx.x == 0) sg[t] = 1.f / (1.f + __expf(-d));
}

// ---------------- flash attention v3: Q fragments in registers, 2 CTAs/SM ----------------
// smem (u32): stage0{K[32][132],V[32][136]} | stage1{...} | Ps[4][16][36]
// Q is staged through stage0 before the pipeline starts, then lives in registers.
#define FAK_LD 132
#define FAV_LD 136
#define FAP_LD 36
#define FA_KVST (32*FAK_LD + 32*FAV_LD)
#define FA_PS   (2*FA_KVST)
#define FA_TOT  (FA_PS + 4*16*FAP_LD)      // 19456 u32 = 77824 B -> 2 CTAs/SM
#define ATTN_SCALE 0.08838834764831845f

__global__ void __launch_bounds__(128, 2)
flash_attn_kernel(const float* __restrict__ Q, const float* __restrict__ K,
                  const float* __restrict__ V, float* __restrict__ O)
{
    extern __shared__ uint32_t sh[];
    const int qb   = (gridDim.x - 1) - blockIdx.x;   // heavy tiles first
    const int hh   = blockIdx.y;
    const int tid  = threadIdx.x;
    const int lane = tid & 31;
    const int warp = tid >> 5;
    const int g    = lane >> 2;
    const int tg   = lane & 3;
    const int wm   = warp * 16;
    const int q0   = qb * 64;
    const long long hoff = (long long)hh * HD;

    const uint32_t shbase = (uint32_t)__cvta_generic_to_shared(sh);

    // ---- stage Q through stage-0 region (64 rows x 132), extract fragments ----
    #pragma unroll
    for (int j = 0; j < 16; j++) {
        int idx = tid + 128 * j;
        int r = idx >> 5, c4 = (idx & 31) * 4;
        float4 t = *reinterpret_cast<const float4*>(&Q[(long long)(q0 + r) * H + hoff + c4]);
        uint4 v = make_uint4(f2tf32(t.x * ATTN_SCALE), f2tf32(t.y * ATTN_SCALE),
                             f2tf32(t.z * ATTN_SCALE), f2tf32(t.w * ATTN_SCALE));
        *reinterpret_cast<uint4*>(&sh[r * FAK_LD + c4]) = v;
    }
    __syncthreads();

    uint32_t qf[16][4];   // Q fragments for all 16 k8-steps, held in registers
    #pragma unroll
    for (int j = 0; j < 16; j++) {
        int kk = j * 8;
        qf[j][0] = sh[(wm + g) * FAK_LD + kk + tg];
        qf[j][1] = sh[(wm + g + 8) * FAK_LD + kk + tg];
        qf[j][2] = sh[(wm + g) * FAK_LD + kk + tg + 4];
        qf[j][3] = sh[(wm + g + 8) * FAK_LD + kk + tg + 4];
    }
    __syncthreads();   // stage-0 region free for KV pipeline

    const int ldrow = tid >> 5;
    const int ldc4  = (tid & 31) * 4;

    auto issue_chunk = [&](int c, int s) {
        uint32_t kbase = shbase + (s * FA_KVST) * 4;
        uint32_t vbase = kbase + 32 * FAK_LD * 4;
        #pragma unroll
        for (int j = 0; j < 8; j++) {
            int r = ldrow + 4 * j;
            long long gofs = (long long)(c * 32 + r) * H + hoff + ldc4;
            cp_async16(kbase + (r * FAK_LD + ldc4) * 4, &K[gofs]);
            cp_async16(vbase + (r * FAV_LD + ldc4) * 4, &V[gofs]);
        }
        cp_commit();
    };

    float Oacc[16][4];
    #pragma unroll
    for (int nt = 0; nt < 16; nt++)
        #pragma unroll
        for (int c = 0; c < 4; c++) Oacc[nt][c] = 0.f;
    float m0r = -1e30f, m1r = -1e30f, l0r = 0.f, l1r = 0.f;

    uint32_t* Pw = &sh[FA_PS + warp * 16 * FAP_LD];
    const int nc = 2 * qb + 2;

    issue_chunk(0, 0);

    for (int c = 0; c < nc; c++) {
        cp_wait0();
        __syncthreads();
        if (c + 1 < nc) issue_chunk(c + 1, (c + 1) & 1);

        const uint32_t* K_ = &sh[(c & 1) * FA_KVST];
        const uint32_t* V_ = K_ + 32 * FAK_LD;

        // S = Q @ K^T : per warp 16x32 (Q frags from registers)
        float Sacc[4][4];
        #pragma unroll
        for (int nt = 0; nt < 4; nt++)
            #pragma unroll
            for (int cc = 0; cc < 4; cc++) Sacc[nt][cc] = 0.f;

        #pragma unroll
        for (int j = 0; j < 16; j++) {
            int kk = j * 8;
            #pragma unroll
            for (int nt = 0; nt < 4; nt++) {
                uint32_t b0 = K_[(nt * 8 + g) * FAK_LD + kk + tg];
                uint32_t b1 = K_[(nt * 8 + g) * FAK_LD + kk + tg + 4];
                mma_tf32(Sacc[nt][0], Sacc[nt][1], Sacc[nt][2], Sacc[nt][3],
                         qf[j][0], qf[j][1], qf[j][2], qf[j][3], b0, b1);
            }
        }

        if (c >= 2 * qb) {
            int r0g = q0 + wm + g, r1g = r0g + 8;
            #pragma unroll
            for (int nt = 0; nt < 4; nt++) {
                int c0 = c * 32 + nt * 8 + 2 * tg, c1 = c0 + 1;
                if (c0 > r0g) Sacc[nt][0] = -1e30f;
                if (c1 > r0g) Sacc[nt][1] = -1e30f;
                if (c0 > r1g) Sacc[nt][2] = -1e30f;
                if (c1 > r1g) Sacc[nt][3] = -1e30f;
            }
        }

        float rmax0 = -1e30f, rmax1 = -1e30f;
        #pragma unroll
        for (int nt = 0; nt < 4; nt++) {
            rmax0 = fmaxf(rmax0, fmaxf(Sacc[nt][0], Sacc[nt][1]));
            rmax1 = fmaxf(rmax1, fmaxf(Sacc[nt][2], Sacc[nt][3]));
        }
        rmax0 = fmaxf(rmax0, __shfl_xor_sync(0xffffffffu, rmax0, 1));
        rmax0 = fmaxf(rmax0, __shfl_xor_sync(0xffffffffu, rmax0, 2));
        rmax1 = fmaxf(rmax1, __shfl_xor_sync(0xffffffffu, rmax1, 1));
        rmax1 = fmaxf(rmax1, __shfl_xor_sync(0xffffffffu, rmax1, 2));

        float nm0 = fmaxf(m0r, rmax0), nm1 = fmaxf(m1r, rmax1);
        float al0 = __expf(m0r - nm0), al1 = __expf(m1r - nm1);
        float sum0 = 0.f, sum1 = 0.f;
        #pragma unroll
        for (int nt = 0; nt < 4; nt++) {
            float p00 = __expf(Sacc[nt][0] - nm0);
            float p01 = __expf(Sacc[nt][1] - nm0);
            float p10 = __expf(Sacc[nt][2] - nm1);
            float p11 = __expf(Sacc[nt][3] - nm1);
            sum0 += p00 + p01; sum1 += p10 + p11;
            int cl = nt * 8 + 2 * tg;
            Pw[g * FAP_LD + cl]           = f2tf32(p00);
            Pw[g * FAP_LD + cl + 1]       = f2tf32(p01);
            Pw[(g + 8) * FAP_LD + cl]     = f2tf32(p10);
            Pw[(g + 8) * FAP_LD + cl + 1] = f2tf32(p11);
        }
        sum0 += __shfl_xor_sync(0xffffffffu, sum0, 1);
        sum0 += __shfl_xor_sync(0xffffffffu, sum0, 2);
        sum1 += __shfl_xor_sync(0xffffffffu, sum1, 1);
        sum1 += __shfl_xor_sync(0xffffffffu, sum1, 2);
        l0r = l0r * al0 + sum0;
        l1r = l1r * al1 + sum1;
        m0r = nm0; m1r = nm1;

        #pragma unroll
        for (int nt = 0; nt < 16; nt++) {
            Oacc[nt][0] *= al0; Oacc[nt][1] *= al0;
            Oacc[nt][2] *= al1; Oacc[nt][3] *= al1;
        }

        __syncwarp();

        // PV: O += P[16x32] @ V[32x128]
        #pragma unroll
        for (int kk = 0; kk < 32; kk += 8) {
            uint32_t a0 = Pw[g * FAP_LD + kk + tg];
            uint32_t a1 = Pw[(g + 8) * FAP_LD + kk + tg];
            uint32_t a2 = Pw[g * FAP_LD + kk + tg + 4];
            uint32_t a3 = Pw[(g + 8) * FAP_LD + kk + tg + 4];
            #pragma unroll
            for (int nt = 0; nt < 16; nt++) {
                uint32_t b0 = V_[(kk + tg) * FAV_LD + nt * 8 + g];
                uint32_t b1 = V_[(kk + tg + 4) * FAV_LD + nt * 8 + g];
                mma_tf32(Oacc[nt][0], Oacc[nt][1], Oacc[nt][2], Oacc[nt][3],
                         a0, a1, a2, a3, b0, b1);
            }
        }
    }

    float inv0 = 1.f / l0r, inv1 = 1.f / l1r;
    long long r0 = q0 + wm + g, r1 = r0 + 8;
    #pragma unroll
    for (int nt = 0; nt < 16; nt++) {
        int c = nt * 8 + 2 * tg;
        *reinterpret_cast<float2*>(&O[r0 * H + hoff + c]) =
            make_float2(Oacc[nt][0] * inv0, Oacc[nt][1] * inv0);
        *reinterpret_cast<float2*>(&O[r1 * H + hoff + c]) =
            make_float2(Oacc[nt][2] * inv1, Oacc[nt][3] * inv1);
    }
}

// ---------------- elementwise / norm ----------------
__global__ void rmsnorm_kernel(const float* __restrict__ x, const float* __restrict__ w,
                               float* __restrict__ y) {
    int t = blockIdx.x;
    const float4* xr = reinterpret_cast<const float4*>(x + (long long)t * H);
    const float4* w4 = reinterpret_cast<const float4*>(w);
    float4* yr = reinterpret_cast<float4*>(y + (long long)t * H);
    float s = 0.f;
    for (int i = threadIdx.x; i < H / 4; i += blockDim.x) {
        float4 v = xr[i];
        s += v.x * v.x + v.y * v.y + v.z * v.z + v.w * v.w;
    }
    s = blockReduceSum(s);
    float scale = rsqrtf(s / (float)H + EPS);
    for (int i = threadIdx.x; i < H / 4; i += blockDim.x) {
        float4 v = xr[i], ww = w4[i];
        yr[i] = make_float4(v.x * scale * ww.x, v.y * scale * ww.y,
                            v.z * scale * ww.z, v.w * scale * ww.w);
    }
}

// merged silu*mul: grid (S, 20)
__global__ void silumul_all_kernel(float4* __restrict__ gbuf, const float4* __restrict__ ubuf,
                                   float* __restrict__ gs, const float* __restrict__ us,
                                   const int* __restrict__ cnt)
{
    int e = blockIdx.y, slot = blockIdx.x;
    float4* gp; const float4* up;
    if (e < E) {
        if (slot >= cnt[e]) return;
        long long base = ((long long)e * S + slot) * (IM / 4);
        gp = gbuf + base;
        up = ubuf + base;
    } else {
        long long off = (long long)slot * IS + (e - E) * 1408;
        gp = reinterpret_cast<float4*>(gs + off);
        up = reinterpret_cast<const float4*>(us + off);
    }
    for (int i = threadIdx.x; i < IM / 4; i += blockDim.x) {
        float4 x = gp[i], y = up[i];
        x.x = (x.x / (1.f + __expf(-x.x))) * y.x;
        x.y = (x.y / (1.f + __expf(-x.y))) * y.y;
        x.z = (x.z / (1.f + __expf(-x.z))) * y.z;
        x.w = (x.w / (1.f + __expf(-x.w))) * y.w;
        gp[i] = x;
    }
}

// ---------------- MoE routing ----------------
__global__ void routing_kernel(const float* __restrict__ logits, int* __restrict__ cnt,
                               int* __restrict__ tke, int* __restrict__ tks,
                               float* __restrict__ tkw, int* __restrict__ tok) {
    int t = blockIdx.x * blockDim.x + threadIdx.x;
    if (t >= S) return;
    float p[E];
    float mx = -3.4e38f;
    #pragma unroll
    for (int e = 0; e < E; e++) { p[e] = logits[t * E + e]; mx = fmaxf(mx, p[e]); }
    float sum = 0.f;
    #pragma unroll
    for (int e = 0; e < E; e++) { p[e] = __expf(p[e] - mx); sum += p[e]; }
    float inv = 1.f / sum;
    #pragma unroll
    for (int e = 0; e < E; e++) p[e] *= inv;
    int ids[TOPK]; float ws[TOPK]; float wsum = 0.f;
    #pragma unroll
    for (int k = 0; k < TOPK; k++) {
        float bv = -1.f; int bi = 0;
        #pragma unroll
        for (int e = 0; e < E; e++) if (p[e] > bv) { bv = p[e]; bi = e; }
        ids[k] = bi; ws[k] = bv; wsum += bv; p[bi] = -2.f;
    }
    float wi = 1.f / wsum;
    #pragma unroll
    for (int k = 0; k < TOPK; k++) {
        int slot = atomicAdd(&cnt[ids[k]], 1);
        tke[t * TOPK + k] = ids[k];
        tks[t * TOPK + k] = slot;
        tkw[t * TOPK + k] = ws[k] * wi;
        tok[ids[k] * S + slot] = t;
    }
}

// fused combine: shared = sum of 4 down-partial slabs (in part); out = sg*shared + Σ w*y
__global__ void combine_kernel(const float* __restrict__ P, const float* __restrict__ sg,
                               const float* __restrict__ ybuf,
                               const int* __restrict__ tke, const int* __restrict__ tks,
                               const float* __restrict__ tkw, float* __restrict__ out) {
    const long long SH = (long long)S * H;
    int t = blockIdx.x;
    float gg = sg[t];
    int e0 = tke[t*4+0], e1 = tke[t*4+1], e2 = tke[t*4+2], e3 = tke[t*4+3];
    int s0 = tks[t*4+0], s1 = tks[t*4+1], s2 = tks[t*4+2], s3 = tks[t*4+3];
    float w0 = tkw[t*4+0], w1 = tkw[t*4+1], w2 = tkw[t*4+2], w3 = tkw[t*4+3];
    const float4* y0 = reinterpret_cast<const float4*>(ybuf + ((long long)e0 * S + s0) * H);
    const float4* y1 = reinterpret_cast<const float4*>(ybuf + ((long long)e1 * S + s1) * H);
    const float4* y2 = reinterpret_cast<const float4*>(ybuf + ((long long)e2 * S + s2) * H);
    const float4* y3 = reinterpret_cast<const float4*>(ybuf + ((long long)e3 * S + s3) * H);
    const long long rowb = (long long)t * H;
    float4* o = reinterpret_cast<float4*>(out + rowb);
    for (int i = threadIdx.x; i < H / 4; i += blockDim.x) {
        int c = i * 4;
        float4 p0 = *reinterpret_cast<const float4*>(P + rowb + c);
        float4 p1 = *reinterpret_cast<const float4*>(P + SH + rowb + c);
        float4 p2 = *reinterpret_cast<const float4*>(P + 2 * SH + rowb + c);
        float4 p3 = *reinterpret_cast<const float4*>(P + 3 * SH + rowb + c);
        float4 a = make_float4(p0.x + p1.x + p2.x + p3.x, p0.y + p1.y + p2.y + p3.y,
                               p0.z + p1.z + p2.z + p3.z, p0.w + p1.w + p2.w + p3.w);
        float4 b0 = y0[i], b1 = y1[i], b2 = y2[i], b3 = y3[i];
        o[i] = make_float4(
            gg * a.x + w0 * b0.x + w1 * b1.x + w2 * b2.x + w3 * b3.x,
            gg * a.y + w0 * b0.y + w1 * b1.y + w2 * b2.y + w3 * b3.y,
            gg * a.z + w0 * b0.z + w1 * b1.z + w2 * b2.z + w3 * b3.z,
            gg * a.w + w0 * b0.w + w1 * b1.w + w2 * b2.w + w3 * b3.w);
    }
}

// ---------------- host orchestration ----------------
static inline void gemm_ext(const float* A, const GSets& sets, int nsets,
                            int M, int N, int K, int lda, int ldb, int ldc,
                            long long sA, long long sB, long long sC,
                            float alpha, int transB, const int* mcnt, int inner,
                            int nsplit, int ksz, float* part, const int* rowidx,
                            int inner1, int Malt,
                            const float* A2, int lda2, long long aSlice,
                            int ldb2, long long bSlice, int ldc2, long long cSlice,
                            int maxMtiles) {
    dim3 grid((N + 127) / 128, maxMtiles, nsets * inner * nsplit);
    tgemm_kernel<<<grid, 128>>>(A, sets, M, N, K, lda, ldb, ldc, sA, sB, sC,
                                alpha, transB, mcnt, inner, nsplit, ksz, part, rowidx,
                                inner1, Malt, A2, lda2, aSlice, ldb2, bSlice, ldc2, cSlice);
}

static inline void gemm_multi(const float* A, const GSets& sets, int nsets,
                              int M, int N, int K, int lda, int ldb, int ldc,
                              long long sA, long long sB, long long sC,
                              float alpha, int transB, const int* mcnt, int inner,
                              int nsplit = 1, int ksz = 0, float* part = nullptr,
                              const int* rowidx = nullptr) {
    gemm_ext(A, sets, nsets, M, N, K, lda, ldb, ldc, sA, sB, sC, alpha, transB,
             mcnt, inner, nsplit, ksz, part, rowidx,
             inner, 0, nullptr, 0, 0, 0, 0, 0, 0, (M + 127) / 128);
}

extern "C" void kernel_launch(void* const* d_in, const int* in_sizes, int n_in,
                              void* d_out, int out_size) {
    const int*   positions = (const int*)  d_in[0];
    const float* hidden    = (const float*)d_in[1];
    const float* ln1       = (const float*)d_in[2];
    const float* ln2       = (const float*)d_in[3];
    const float* q_w       = (const float*)d_in[4];
    const float* q_b       = (const float*)d_in[5];
    const float* k_w       = (const float*)d_in[6];
    const float* k_b       = (const float*)d_in[7];
    const float* v_w       = (const float*)d_in[8];
    const float* v_b       = (const float*)d_in[9];
    const float* o_w       = (const float*)d_in[10];
    const float* router_w  = (const float*)d_in[11];
    const float* we_gate   = (const float*)d_in[12];
    const float* we_up     = (const float*)d_in[13];
    const float* we_down   = (const float*)d_in[14];
    const float* ws_gate   = (const float*)d_in[15];
    const float* ws_up     = (const float*)d_in[16];
    const float* ws_down   = (const float*)d_in[17];
    const float* wsg       = (const float*)d_in[18];
    float* out = (float*)d_out;

    float *h1, *q, *k, *v, *attn, *h2, *gs, *us;
    float *logits, *sgv, *gbuf, *ubuf, *ybuf, *tkw, *part;
    int *cnt, *tke, *tks, *tok;
    cudaGetSymbolAddress((void**)&h1,     g_h1);
    cudaGetSymbolAddress((void**)&q,      g_q);
    cudaGetSymbolAddress((void**)&k,      g_k);
    cudaGetSymbolAddress((void**)&v,      g_v);
    cudaGetSymbolAddress((void**)&attn,   g_attn);
    cudaGetSymbolAddress((void**)&h2,     g_h2);
    cudaGetSymbolAddress((void**)&gs,     g_gs);
    cudaGetSymbolAddress((void**)&us,     g_us);
    cudaGetSymbolAddress((void**)&logits, g_logits);
    cudaGetSymbolAddress((void**)&sgv,    g_sg);
    cudaGetSymbolAddress((void**)&cnt,    g_cnt);
    cudaGetSymbolAddress((void**)&tke,    g_tk_e);
    cudaGetSymbolAddress((void**)&tks,    g_tk_slot);
    cudaGetSymbolAddress((void**)&tkw,    g_tk_w);
    cudaGetSymbolAddress((void**)&tok,    g_tok);
    cudaGetSymbolAddress((void**)&gbuf,   g_gbuf);
    cudaGetSymbolAddress((void**)&ubuf,   g_ubuf);
    cudaGetSymbolAddress((void**)&ybuf,   g_ybuf);
    cudaGetSymbolAddress((void**)&part,   g_part);

    cudaFuncSetAttribute(flash_attn_kernel,
                         cudaFuncAttributeMaxDynamicSharedMemorySize, FA_TOT * 4);

    // --- pre-attention norm + fused QKV (split-K 3) + fused bias/RoPE reduce ---
    rmsnorm_kernel<<<S, 256>>>(hidden, ln1, h1);
    {
        GSets s{};
        s.s[0] = {q_w, nullptr, nullptr, nullptr, nullptr};
        s.s[1] = {k_w, nullptr, nullptr, nullptr, nullptr};
        s.s[2] = {v_w, nullptr, nullptr, nullptr, nullptr};
        gemm_multi(h1, s, 3, S, H, H, H, H, H, 0, 0, 0, 1.f, 0, nullptr, 1,
                   3, 688, part);
        reduce_qkv_rope_kernel<<<S, 256>>>(part, q, k, v, q_b, k_b, v_b, positions);
    }

    // --- fused flash attention (v3: Q-in-regs, 2 CTAs/SM) ---
    flash_attn_kernel<<<dim3(S / 64, NH), 128, FA_TOT * 4>>>(q, k, v, attn);

    // --- O proj (split-K 4) + fused residual/rmsnorm/sgate ---
    {
        GSets s{};
        s.s[0] = {o_w, nullptr, nullptr, nullptr, nullptr};
        gemm_multi(attn, s, 1, S, H, H, H, H, 0, 0, 0, 0,
                   1.f, 0, nullptr, 1, 4, 512, part);
        oproj_rms_sgate_kernel<<<S, 256>>>(part, hidden, ln2, wsg, h2, sgv);
    }

    // --- router (split-K 8) + dispatch ---
    {
        GSets s{};
        s.s[0] = {router_w, nullptr, nullptr, nullptr, nullptr};
        gemm_multi(h2, s, 1, S, E, H, H, E, E, 0, 0, 0,
                   1.f, 0, nullptr, 1, 8, 256, part);
        reduce_logits_zero_kernel<<<(S * E / 4 + 255) / 256, 256>>>(
            (const float4*)part, (float4*)logits, cnt,
            8, (long long)S * E / 4, (long long)S * E / 4);
    }
    routing_kernel<<<(S + 255) / 256, 256>>>(logits, cnt, tke, tks, tkw, tok);

    // --- MERGED gate/up: 16 routed experts + 4 shared-expert N-slices ---
    {
        GSets s{};
        s.s[0] = {we_gate, gbuf, nullptr, ws_gate, gs};
        s.s[1] = {we_up,   ubuf, nullptr, ws_up,   us};
        gemm_ext(h2, s, 2, S, IM, H, H, IM, IM,
                 0, (long long)H * IM, (long long)S * IM,
                 1.f, 0, cnt, 20, 1, 0, nullptr, tok,
                 16, S, h2, H, 0, IS, 1408, IS, 1408, S / 128);
    }
    silumul_all_kernel<<<dim3(S, 20), 256>>>((float4*)gbuf, (const float4*)ubuf,
                                             gs, us, cnt);

    // --- MERGED down: 16 routed experts + 4 shared-expert K-slices (partials) ---
    {
        GSets s{};
        s.s[0] = {we_down, ybuf, nullptr, ws_down, part};
        gemm_ext(gbuf, s, 1, S, H, IM, IM, H, H,
                 (long long)S * IM, (long long)IM * H, (long long)S * H,
                 1.f, 0, cnt, 20, 1, 0, nullptr, nullptr,
                 16, S, gs, IS, 1408, H, (long long)1408 * H, H, (long long)S * H,
                 S / 128);
    }

    // --- final combine (sums shared-expert partials inline) ---
    combine_kernel<<<S, 256>>>(part, sgv, ybuf, tke, tks, tkw, out);
}